// round 1
// baseline (speedup 1.0000x reference)
#include <cuda_runtime.h>
#include <math.h>

#define BATCH 256
#define NCLS  10
#define CC    128   // conv channels
#define OCH   256   // primary-capsule output channels (8*32)

// ---------------- static device scratch (max = branch 3 sizes) ----------------
__device__ float g_x2[BATCH*14*14];
__device__ float g_x1[BATCH*7*7];
__device__ float g_y [BATCH*CC*20*20];                 // conv output / normalized
__device__ float g_mean[CC];
__device__ float g_rstd[CC];
__device__ float g_wT [10368*OCH];                     // transposed prim weights [K][256]
__device__ int   g_ktab[10368];                        // k-index -> input offset
__device__ float g_p [BATCH*OCH*36];                   // primary caps pre-squash
__device__ float g_u [BATCH*1152*8];                   // squashed capsule inputs
__device__ float g_priors[(size_t)NCLS*BATCH*1152*16]; // 189 MB
__device__ float g_len[3*BATCH*NCLS];

// ---------------- pooling ----------------
__global__ void pool2_kernel(const float* __restrict__ img) {
    int idx = blockIdx.x*blockDim.x + threadIdx.x;
    if (idx >= BATCH*14*14) return;
    int j = idx % 14, i = (idx/14) % 14, b = idx/196;
    const float* p = img + b*784;
    g_x2[idx] = 0.25f*(p[(2*i)*28+2*j] + p[(2*i)*28+2*j+1]
                     + p[(2*i+1)*28+2*j] + p[(2*i+1)*28+2*j+1]);
}
__global__ void pool1_kernel() {
    int idx = blockIdx.x*blockDim.x + threadIdx.x;
    if (idx >= BATCH*7*7) return;
    int j = idx % 7, i = (idx/7) % 7, b = idx/49;
    const float* p = g_x2 + b*196;
    g_x1[idx] = 0.25f*(p[(2*i)*14+2*j] + p[(2*i)*14+2*j+1]
                     + p[(2*i+1)*14+2*j] + p[(2*i+1)*14+2*j+1]);
}

// ---------------- conv stage A: 1ch -> 128ch, VALID, stride 1, +bias, relu ----------------
__global__ void convA_kernel(const float* __restrict__ xin_ext, int src,
                             const float* __restrict__ w, const float* __restrict__ bias,
                             int H, int H1, int k)
{
    int idx = blockIdx.x*blockDim.x + threadIdx.x;
    int total = BATCH*CC*H1*H1;
    if (idx >= total) return;
    const float* xin = (src == 0) ? xin_ext : (src == 1 ? g_x2 : g_x1);
    int ox = idx % H1;
    int oy = (idx / H1) % H1;
    int c  = (idx / (H1*H1)) % CC;
    int b  = idx / (CC*H1*H1);
    const float* ip = xin + b*H*H + oy*H + ox;
    const float* wp = w + c*k*k;
    float s = bias[c];
    for (int ky = 0; ky < k; ky++)
        for (int kx = 0; kx < k; kx++)
            s += ip[ky*H + kx] * wp[ky*k + kx];
    g_y[idx] = fmaxf(s, 0.f);
}

// ---------------- batchnorm over (B,H,W) per channel ----------------
__global__ void bn_stats_kernel(int HW) {
    int c = blockIdx.x;
    int tid = threadIdx.x;
    int N = BATCH*HW;
    float s = 0.f, s2 = 0.f;
    for (int i = tid; i < N; i += blockDim.x) {
        int b = i / HW, hw = i - b*HW;
        float v = g_y[(b*CC + c)*HW + hw];
        s += v; s2 += v*v;
    }
    __shared__ float rs[256], rq[256];
    rs[tid] = s; rq[tid] = s2;
    __syncthreads();
    for (int off = 128; off; off >>= 1) {
        if (tid < off) { rs[tid] += rs[tid+off]; rq[tid] += rq[tid+off]; }
        __syncthreads();
    }
    if (tid == 0) {
        float m = rs[0] / (float)N;
        float var = rq[0] / (float)N - m*m;
        g_mean[c] = m;
        g_rstd[c] = rsqrtf(var + 1e-5f);
    }
}
__global__ void bn_apply_kernel(int HW) {
    int idx = blockIdx.x*blockDim.x + threadIdx.x;
    int total = BATCH*CC*HW;
    if (idx >= total) return;
    int c = (idx / HW) % CC;
    g_y[idx] = (g_y[idx] - g_mean[c]) * g_rstd[c];
}

// ---------------- prim conv prep: transpose weights & build im2col offset table ----------------
__global__ void prep_w_kernel(const float* __restrict__ pw, int K) {
    int idx = blockIdx.x*blockDim.x + threadIdx.x;
    if (idx >= K*OCH) return;
    int oc = idx & (OCH-1);
    int kidx = idx >> 8;
    g_wT[idx] = pw[oc*K + kidx];
}
__global__ void prep_ktab_kernel(int K, int kp, int H1) {
    int kidx = blockIdx.x*blockDim.x + threadIdx.x;
    if (kidx >= K) return;
    int kk2 = kp*kp;
    int ic = kidx / kk2;
    int rem = kidx - ic*kk2;
    g_ktab[kidx] = ic*H1*H1 + (rem/kp)*H1 + (rem % kp);
}

// ---------------- prim conv as implicit GEMM: C[M=B*S][N=256], K = 128*kp*kp ----------------
__global__ void prim_gemm_kernel(const float* __restrict__ pb,
                                 int S, int Hp, int H1, int K)
{
    __shared__ __align__(16) float As[16][64];
    __shared__ __align__(16) float Bs[16][64];
    __shared__ int rowbase[64];
    __shared__ int outb[64];

    int tid = threadIdx.x;
    int n0 = blockIdx.x * 64;
    int m0 = blockIdx.y * 64;

    if (tid < 64) {
        int m = m0 + tid;
        int b = m / S, s = m - b*S;
        int oy = s / Hp, ox = s - oy*Hp;
        rowbase[tid] = (b*CC)*H1*H1 + (oy*2)*H1 + ox*2;
        outb[tid]    = (b*OCH)*S + s;
    }
    __syncthreads();

    float acc[4][4];
#pragma unroll
    for (int i = 0; i < 4; i++)
#pragma unroll
        for (int j = 0; j < 4; j++) acc[i][j] = 0.f;

    int tx = tid & 15, ty = tid >> 4;

    for (int k0 = 0; k0 < K; k0 += 16) {
#pragma unroll
        for (int i = 0; i < 4; i++) {
            int l = tid + i*256;
            int mm = l & 63, kk = l >> 6;
            As[kk][mm] = g_y[rowbase[mm] + g_ktab[k0 + kk]];
            Bs[kk][mm] = g_wT[(k0 + kk)*OCH + n0 + mm];
        }
        __syncthreads();
#pragma unroll
        for (int kk = 0; kk < 16; kk++) {
            float4 av = *reinterpret_cast<const float4*>(&As[kk][ty*4]);
            float4 bv = *reinterpret_cast<const float4*>(&Bs[kk][tx*4]);
            float a[4] = {av.x, av.y, av.z, av.w};
            float bb[4] = {bv.x, bv.y, bv.z, bv.w};
#pragma unroll
            for (int i = 0; i < 4; i++)
#pragma unroll
                for (int j = 0; j < 4; j++)
                    acc[i][j] += a[i]*bb[j];
        }
        __syncthreads();
    }

#pragma unroll
    for (int i = 0; i < 4; i++) {
        int ob = outb[ty*4 + i];
#pragma unroll
        for (int j = 0; j < 4; j++) {
            int oc = n0 + tx*4 + j;
            g_p[ob + oc*S] = acc[i][j] + pb[oc];
        }
    }
}

// ---------------- squash primary capsules into u[b][r][8] ----------------
__global__ void squash_u_kernel(int S, int R) {
    int idx = blockIdx.x*blockDim.x + threadIdx.x;
    if (idx >= BATCH*R) return;
    int r = idx % R, b = idx / R;
    int c32 = r / S, s = r - c32*S;
    float t[8]; float sn = 0.f;
#pragma unroll
    for (int i = 0; i < 8; i++) {
        t[i] = g_p[(b*OCH + i*32 + c32)*S + s];
        sn += t[i]*t[i];
    }
    float scale = sn/(1.f + sn) * rsqrtf(sn + 1e-12f);
#pragma unroll
    for (int i = 0; i < 8; i++)
        g_u[idx*8 + i] = t[i]*scale;
}

// ---------------- priors[n][b][r][16] = u[b][r][:] @ dw[n][r][:][:] ----------------
__global__ void priors_kernel(const float* __restrict__ dw, int R) {
    int r = blockIdx.x, n = blockIdx.y;
    __shared__ float w[128];
    if (threadIdx.x < 128)
        w[threadIdx.x] = dw[((size_t)n*R + r)*128 + threadIdx.x];
    __syncthreads();
    int b = threadIdx.x;  // 256 threads == BATCH
    float u[8];
#pragma unroll
    for (int i = 0; i < 8; i++) u[i] = g_u[((size_t)b*R + r)*8 + i];
    float* out = g_priors + (((size_t)n*BATCH + b)*R + r)*16;
#pragma unroll
    for (int o = 0; o < 16; o++) {
        float s = 0.f;
#pragma unroll
        for (int i = 0; i < 8; i++) s += u[i]*w[i*16 + o];
        out[o] = s;
    }
}

// ---------------- dynamic routing: one block per (n,b), 3 iterations ----------------
__global__ void routing_kernel(int R, int br) {
    int b = blockIdx.x, n = blockIdx.y;
    extern __shared__ float sm[];
    float* P    = sm;            // R*16
    float* blog = P + R*16;      // R
    float* wred = blog + R;      // 8*16
    float* vv   = wred + 128;    // 16
    float* sred = vv + 16;       // 8
    float* scal = sred + 8;      // 2

    int tid = threadIdx.x;
    const float* gp = g_priors + (((size_t)n*BATCH + b)*R)*16;
    for (int i = tid; i < R*16; i += 256) P[i] = gp[i];
    for (int r = tid; r < R;    r += 256) blog[r] = 0.f;
    __syncthreads();

    for (int it = 0; it < 3; it++) {
        // --- softmax over r: max ---
        float mx = -1e30f;
        for (int r = tid; r < R; r += 256) mx = fmaxf(mx, blog[r]);
#pragma unroll
        for (int off = 16; off; off >>= 1)
            mx = fmaxf(mx, __shfl_xor_sync(0xffffffffu, mx, off));
        if ((tid & 31) == 0) sred[tid >> 5] = mx;
        __syncthreads();
        if (tid == 0) {
            float m = sred[0];
            for (int w2 = 1; w2 < 8; w2++) m = fmaxf(m, sred[w2]);
            scal[0] = m;
        }
        __syncthreads();
        float gmax = scal[0];
        // --- sum of exp ---
        float se = 0.f;
        for (int r = tid; r < R; r += 256) se += expf(blog[r] - gmax);
#pragma unroll
        for (int off = 16; off; off >>= 1)
            se += __shfl_xor_sync(0xffffffffu, se, off);
        if ((tid & 31) == 0) sred[tid >> 5] = se;
        __syncthreads();
        if (tid == 0) {
            float s = 0.f;
            for (int w2 = 0; w2 < 8; w2++) s += sred[w2];
            scal[1] = 1.f/s;
        }
        __syncthreads();
        float isum = scal[1];
        // --- weighted sum of priors ---
        float acc[16];
#pragma unroll
        for (int o = 0; o < 16; o++) acc[o] = 0.f;
        for (int r = tid; r < R; r += 256) {
            float c = expf(blog[r] - gmax)*isum;
            const float* pr = P + r*16;
#pragma unroll
            for (int o = 0; o < 16; o++) acc[o] += c*pr[o];
        }
#pragma unroll
        for (int o = 0; o < 16; o++) {
            float v = acc[o];
#pragma unroll
            for (int off = 16; off; off >>= 1)
                v += __shfl_xor_sync(0xffffffffu, v, off);
            acc[o] = v;
        }
        if ((tid & 31) == 0)
#pragma unroll
            for (int o = 0; o < 16; o++) wred[(tid >> 5)*16 + o] = acc[o];
        __syncthreads();
        if (tid == 0) {
            float s16[16]; float sn = 0.f;
#pragma unroll
            for (int o = 0; o < 16; o++) {
                float s = 0.f;
                for (int w2 = 0; w2 < 8; w2++) s += wred[w2*16 + o];
                s16[o] = s; sn += s*s;
            }
            float sc = sn/(1.f + sn) * rsqrtf(sn + 1e-12f);
#pragma unroll
            for (int o = 0; o < 16; o++) vv[o] = s16[o]*sc;
        }
        __syncthreads();
        if (it < 2) {
            for (int r = tid; r < R; r += 256) {
                const float* pr = P + r*16;
                float d = 0.f;
#pragma unroll
                for (int o = 0; o < 16; o++) d += pr[o]*vv[o];
                blog[r] += d;
            }
            __syncthreads();
        }
    }
    if (tid == 0) {
        float s = 0.f;
#pragma unroll
        for (int o = 0; o < 16; o++) s += vv[o]*vv[o];
        g_len[br*BATCH*NCLS + b*NCLS + n] = sqrtf(s + 1e-12f);
    }
}

// ---------------- final: softmax(l1+l2+l3) ----------------
__global__ void final_kernel(float* __restrict__ out) {
    int b = blockIdx.x*blockDim.x + threadIdx.x;
    if (b >= BATCH) return;
    float l[NCLS]; float mx = -1e30f;
#pragma unroll
    for (int n = 0; n < NCLS; n++) {
        l[n] = g_len[0*BATCH*NCLS + b*NCLS + n]
             + g_len[1*BATCH*NCLS + b*NCLS + n]
             + g_len[2*BATCH*NCLS + b*NCLS + n];
        mx = fmaxf(mx, l[n]);
    }
    float s = 0.f;
#pragma unroll
    for (int n = 0; n < NCLS; n++) { l[n] = expf(l[n] - mx); s += l[n]; }
    float inv = 1.f/s;
#pragma unroll
    for (int n = 0; n < NCLS; n++) out[b*NCLS + n] = l[n]*inv;
}

// ---------------- host driver ----------------
struct BranchCfg {
    int src;           // 0: x(28), 1: g_x2(14), 2: g_x1(7)
    int H, k1, H1, kp, Hp, S, R, K;
    int iw;            // first input index for this branch's weights
};

static void run_branch(const BranchCfg& c, void* const* d_in, const float* x, int br)
{
    const float* cw = (const float*)d_in[c.iw + 0];
    const float* cb = (const float*)d_in[c.iw + 1];
    const float* pw = (const float*)d_in[c.iw + 2];
    const float* pb = (const float*)d_in[c.iw + 3];
    const float* dw = (const float*)d_in[c.iw + 4];

    int HW = c.H1*c.H1;
    int totalA = BATCH*CC*HW;
    convA_kernel<<<(totalA + 255)/256, 256>>>(x, c.src, cw, cb, c.H, c.H1, c.k1);
    bn_stats_kernel<<<CC, 256>>>(HW);
    bn_apply_kernel<<<(totalA + 255)/256, 256>>>(HW);

    prep_w_kernel<<<(c.K*OCH + 255)/256, 256>>>(pw, c.K);
    prep_ktab_kernel<<<(c.K + 255)/256, 256>>>(c.K, c.kp, c.H1);

    int M = BATCH*c.S;
    dim3 ggrid(OCH/64, M/64);
    prim_gemm_kernel<<<ggrid, 256>>>(pb, c.S, c.Hp, c.H1, c.K);

    squash_u_kernel<<<(BATCH*c.R + 255)/256, 256>>>(c.S, c.R);

    dim3 pgrid(c.R, NCLS);
    priors_kernel<<<pgrid, 256>>>(dw, c.R);

    int smem = (c.R*17 + 128 + 16 + 8 + 2)*(int)sizeof(float);
    dim3 rgrid(BATCH, NCLS);
    routing_kernel<<<rgrid, 256, smem>>>(c.R, br);
}

extern "C" void kernel_launch(void* const* d_in, const int* in_sizes, int n_in,
                              void* d_out, int out_size)
{
    (void)in_sizes; (void)n_in; (void)out_size;
    const float* x = (const float*)d_in[0];
    float* out = (float*)d_out;

    cudaFuncSetAttribute(routing_kernel, cudaFuncAttributeMaxDynamicSharedMemorySize, 96*1024);

    pool2_kernel<<<(BATCH*14*14 + 255)/256, 256>>>(x);
    pool1_kernel<<<(BATCH*7*7 + 255)/256, 256>>>();

    //                src  H  k1 H1  kp Hp  S    R      K   iw
    BranchCfg b1 = {   2,  7, 3,  5,  3, 2,  4,  128,  1152,  1 };
    BranchCfg b2 = {   1, 14, 5, 10,  5, 3,  9,  288,  3200,  6 };
    BranchCfg b3 = {   0, 28, 9, 20,  9, 6, 36, 1152, 10368, 11 };

    run_branch(b1, d_in, x, 0);
    run_branch(b2, d_in, x, 1);
    run_branch(b3, d_in, x, 2);

    final_kernel<<<1, 256>>>(out);
}

// round 3
// speedup vs baseline: 1.3744x; 1.3744x over previous
#include <cuda_runtime.h>
#include <cuda_bf16.h>
#include <math.h>
#include <stdint.h>

#define BATCH 256
#define NCLS  10
#define CC    128
#define OCH   256

// GEMM tiling
#define TSTRIDE 40            // bf16 elems per smem row (80B, 16B-aligned)
#define TILEB   (128*TSTRIDE*2)   // 10240 B per 128x32 bf16 tile
#define STAGEB  (4*TILEB)         // Ah,Al,Bh,Bl = 40960 B
#define GSMEM   (2*STAGEB)        // double buffered = 81920 B

// ---------------- static device scratch (max = branch 3 sizes) ----------------
__device__ float g_x2[BATCH*14*14];
__device__ float g_x1[BATCH*7*7];
__device__ float g_y [BATCH*CC*20*20];
__device__ float g_mean[CC];
__device__ float g_rstd[CC];
__device__ int   g_ktab[10368];
__device__ __nv_bfloat16 g_wh[(size_t)OCH*10368];
__device__ __nv_bfloat16 g_wl[(size_t)OCH*10368];
__device__ __nv_bfloat16 g_Ah[(size_t)9216*10368];
__device__ __nv_bfloat16 g_Al[(size_t)9216*10368];
__device__ float g_p [BATCH*OCH*36];
__device__ float g_u [BATCH*1152*8];
__device__ float g_priors[(size_t)NCLS*BATCH*1152*16];
__device__ float g_len[3*BATCH*NCLS];

// ---------------- PTX helpers ----------------
__device__ __forceinline__ uint32_t smem_u32(const void* p) {
    uint32_t a;
    asm("{ .reg .u64 t; cvta.to.shared.u64 t, %1; cvt.u32.u64 %0, t; }" : "=r"(a) : "l"(p));
    return a;
}
#define CP_ASYNC16(dst, src) \
    asm volatile("cp.async.ca.shared.global [%0], [%1], 16;" :: "r"(dst), "l"(src) : "memory")
#define CP_COMMIT() asm volatile("cp.async.commit_group;" ::: "memory")
#define CP_WAIT0()  asm volatile("cp.async.wait_group 0;" ::: "memory")
#define CP_WAIT1()  asm volatile("cp.async.wait_group 1;" ::: "memory")

__device__ __forceinline__ void ldmx4(uint32_t addr, uint32_t& r0, uint32_t& r1,
                                      uint32_t& r2, uint32_t& r3) {
    asm volatile("ldmatrix.sync.aligned.m8n8.x4.shared.b16 {%0,%1,%2,%3}, [%4];"
                 : "=r"(r0), "=r"(r1), "=r"(r2), "=r"(r3) : "r"(addr));
}
__device__ __forceinline__ void mma16816(float* c, const uint32_t* a, uint32_t b0, uint32_t b1) {
    asm volatile(
        "mma.sync.aligned.m16n8k16.row.col.f32.bf16.bf16.f32 "
        "{%0,%1,%2,%3}, {%4,%5,%6,%7}, {%8,%9}, {%0,%1,%2,%3};"
        : "+f"(c[0]), "+f"(c[1]), "+f"(c[2]), "+f"(c[3])
        : "r"(a[0]), "r"(a[1]), "r"(a[2]), "r"(a[3]), "r"(b0), "r"(b1));
}

// ---------------- pooling ----------------
__global__ void pool2_kernel(const float* __restrict__ img) {
    int idx = blockIdx.x*blockDim.x + threadIdx.x;
    if (idx >= BATCH*14*14) return;
    int j = idx % 14, i = (idx/14) % 14, b = idx/196;
    const float* p = img + b*784;
    g_x2[idx] = 0.25f*(p[(2*i)*28+2*j] + p[(2*i)*28+2*j+1]
                     + p[(2*i+1)*28+2*j] + p[(2*i+1)*28+2*j+1]);
}
__global__ void pool1_kernel() {
    int idx = blockIdx.x*blockDim.x + threadIdx.x;
    if (idx >= BATCH*7*7) return;
    int j = idx % 7, i = (idx/7) % 7, b = idx/49;
    const float* p = g_x2 + b*196;
    g_x1[idx] = 0.25f*(p[(2*i)*14+2*j] + p[(2*i)*14+2*j+1]
                     + p[(2*i+1)*14+2*j] + p[(2*i+1)*14+2*j+1]);
}

// ---------------- conv stage A ----------------
__global__ void convA_kernel(const float* __restrict__ xin_ext, int src,
                             const float* __restrict__ w, const float* __restrict__ bias,
                             int H, int H1, int k)
{
    int idx = blockIdx.x*blockDim.x + threadIdx.x;
    int total = BATCH*CC*H1*H1;
    if (idx >= total) return;
    const float* xin = (src == 0) ? xin_ext : (src == 1 ? g_x2 : g_x1);
    int ox = idx % H1;
    int oy = (idx / H1) % H1;
    int c  = (idx / (H1*H1)) % CC;
    int b  = idx / (CC*H1*H1);
    const float* ip = xin + b*H*H + oy*H + ox;
    const float* wp = w + c*k*k;
    float s = bias[c];
    for (int ky = 0; ky < k; ky++)
        for (int kx = 0; kx < k; kx++)
            s += ip[ky*H + kx] * wp[ky*k + kx];
    g_y[idx] = fmaxf(s, 0.f);
}

// ---------------- batchnorm ----------------
__global__ void bn_stats_kernel(int HW) {
    int c = blockIdx.x;
    int tid = threadIdx.x;
    int N = BATCH*HW;
    float s = 0.f, s2 = 0.f;
    for (int i = tid; i < N; i += blockDim.x) {
        int b = i / HW, hw = i - b*HW;
        float v = g_y[(b*CC + c)*HW + hw];
        s += v; s2 += v*v;
    }
    __shared__ float rs[256], rq[256];
    rs[tid] = s; rq[tid] = s2;
    __syncthreads();
    for (int off = 128; off; off >>= 1) {
        if (tid < off) { rs[tid] += rs[tid+off]; rq[tid] += rq[tid+off]; }
        __syncthreads();
    }
    if (tid == 0) {
        float m = rs[0] / (float)N;
        float var = rq[0] / (float)N - m*m;
        g_mean[c] = m;
        g_rstd[c] = rsqrtf(var + 1e-5f);
    }
}
__global__ void bn_apply_kernel(int HW) {
    int idx = blockIdx.x*blockDim.x + threadIdx.x;
    int total = BATCH*CC*HW;
    if (idx >= total) return;
    int c = (idx / HW) % CC;
    g_y[idx] = (g_y[idx] - g_mean[c]) * g_rstd[c];
}

// ---------------- prep: split weights, ktab, im2col split A ----------------
__global__ void prep_w_kernel(const float* __restrict__ pw, int K) {
    int idx = blockIdx.x*blockDim.x + threadIdx.x;
    if (idx >= OCH*K) return;
    float v = pw[idx];
    __nv_bfloat16 h = __float2bfloat16(v);
    g_wh[idx] = h;
    g_wl[idx] = __float2bfloat16(v - __bfloat162float(h));
}
__global__ void prep_ktab_kernel(int K, int kp, int H1) {
    int kidx = blockIdx.x*blockDim.x + threadIdx.x;
    if (kidx >= K) return;
    int kk2 = kp*kp;
    int ic = kidx / kk2;
    int rem = kidx - ic*kk2;
    g_ktab[kidx] = ic*H1*H1 + (rem/kp)*H1 + (rem % kp);
}
__global__ void im2col_kernel(int S, int Hp, int H1, int K) {
    int m = blockIdx.x;
    int b = m / S, s = m - b*S;
    int oy = s / Hp, ox = s - oy*Hp;
    const float* src = g_y + (b*CC)*H1*H1 + (oy*2)*H1 + ox*2;
    size_t base = (size_t)m*K;
    for (int k = threadIdx.x; k < K; k += blockDim.x) {
        float v = src[g_ktab[k]];
        __nv_bfloat16 h = __float2bfloat16(v);
        g_Ah[base + k] = h;
        g_Al[base + k] = __float2bfloat16(v - __bfloat162float(h));
    }
}

// ---------------- prim conv GEMM: mma.sync bf16 split, 128x128 tile ----------------
__device__ __forceinline__ void load_stage(uint32_t sb, int buf,
                                           int m0, int n0, int kc, int K, int tid)
{
    uint32_t dst0 = sb + buf*STAGEB;
#pragma unroll
    for (int i = 0; i < 8; i++) {
        int q = tid + i*256;
        int mat = q >> 9;              // 0:Ah 1:Al 2:Bh 3:Bl
        int w = q & 511;
        int row = w >> 2;
        int ch  = w & 3;
        const __nv_bfloat16* gsrc;
        if      (mat == 0) gsrc = g_Ah + (size_t)(m0 + row)*K + kc + ch*8;
        else if (mat == 1) gsrc = g_Al + (size_t)(m0 + row)*K + kc + ch*8;
        else if (mat == 2) gsrc = g_wh + (size_t)(n0 + row)*K + kc + ch*8;
        else               gsrc = g_wl + (size_t)(n0 + row)*K + kc + ch*8;
        uint32_t dst = dst0 + mat*TILEB + row*(TSTRIDE*2) + ch*16;
        CP_ASYNC16(dst, gsrc);
    }
}

__global__ __launch_bounds__(256) void prim_mma_kernel(const float* __restrict__ pb, int S, int K)
{
    extern __shared__ char smem[];
    uint32_t sb = smem_u32(smem);
    int tid = threadIdx.x, wid = tid >> 5, lane = tid & 31;
    int n0 = (blockIdx.x & 1) << 7;
    int m0 = (int)(blockIdx.x >> 1) << 7;

    int wm = (wid & 3) << 5;   // warp m-origin within tile (32-row slab)
    int wn = (wid >> 2) << 6;  // warp n-origin within tile (64-col slab)

    float acc[2][8][4];
#pragma unroll
    for (int mt = 0; mt < 2; mt++)
#pragma unroll
        for (int nb = 0; nb < 8; nb++)
#pragma unroll
            for (int j = 0; j < 4; j++) acc[mt][nb][j] = 0.f;

    int nch = K >> 5;
    load_stage(sb, 0, m0, n0, 0, K, tid);
    CP_COMMIT();

    // precomputed lane offsets (bytes within a tile)
    uint32_t aLaneOff = (uint32_t)((lane & 15)*(TSTRIDE*2) + (lane >> 4)*16);
    uint32_t bLaneOff = (uint32_t)((((lane >> 3) & 3)*8 + (lane & 7))*(TSTRIDE*2));

    for (int c = 0; c < nch; c++) {
        int buf = c & 1;
        if (c + 1 < nch) {
            load_stage(sb, buf ^ 1, m0, n0, (c + 1) << 5, K, tid);
            CP_COMMIT();
            CP_WAIT1();
        } else {
            CP_WAIT0();
        }
        __syncthreads();

        uint32_t st = sb + buf*STAGEB;
#pragma unroll
        for (int pass = 0; pass < 3; pass++) {
            uint32_t aBase = st + ((pass == 2) ? TILEB : 0);
            uint32_t bBase = st + ((pass == 1) ? 3*TILEB : 2*TILEB);
#pragma unroll
            for (int kk = 0; kk < 2; kk++) {
                uint32_t a[2][4];
#pragma unroll
                for (int mt = 0; mt < 2; mt++)
                    ldmx4(aBase + (wm + mt*16)*(TSTRIDE*2) + kk*32 + aLaneOff,
                          a[mt][0], a[mt][1], a[mt][2], a[mt][3]);
                uint32_t b[8][2];
#pragma unroll
                for (int g = 0; g < 2; g++)
#pragma unroll
                    for (int kh = 0; kh < 2; kh++) {
                        uint32_t r0, r1, r2, r3;
                        ldmx4(bBase + (wn + g*32)*(TSTRIDE*2) + kk*32 + kh*16 + bLaneOff,
                              r0, r1, r2, r3);
                        b[g*4+0][kh] = r0; b[g*4+1][kh] = r1;
                        b[g*4+2][kh] = r2; b[g*4+3][kh] = r3;
                    }
#pragma unroll
                for (int mt = 0; mt < 2; mt++)
#pragma unroll
                    for (int nb = 0; nb < 8; nb++)
                        mma16816(acc[mt][nb], a[mt], b[nb][0], b[nb][1]);
            }
        }
        __syncthreads();
    }

    // epilogue: scatter to g_p[(b*OCH+oc)*S + s] with bias
    int gr = lane >> 2, tc = lane & 3;
#pragma unroll
    for (int mt = 0; mt < 2; mt++) {
        int mA = m0 + wm + mt*16 + gr;
        int mB = mA + 8;
        int bA = mA / S, sA2 = mA - bA*S;
        int bB = mB / S, sB2 = mB - bB*S;
#pragma unroll
        for (int nb = 0; nb < 8; nb++) {
            int oc = n0 + wn + nb*8 + tc*2;
            float bias0 = pb[oc], bias1 = pb[oc+1];
            g_p[(size_t)(bA*OCH + oc    )*S + sA2] = acc[mt][nb][0] + bias0;
            g_p[(size_t)(bA*OCH + oc + 1)*S + sA2] = acc[mt][nb][1] + bias1;
            g_p[(size_t)(bB*OCH + oc    )*S + sB2] = acc[mt][nb][2] + bias0;
            g_p[(size_t)(bB*OCH + oc + 1)*S + sB2] = acc[mt][nb][3] + bias1;
        }
    }
}

// ---------------- squash primary capsules ----------------
__global__ void squash_u_kernel(int S, int R) {
    int idx = blockIdx.x*blockDim.x + threadIdx.x;
    if (idx >= BATCH*R) return;
    int r = idx % R, b = idx / R;
    int c32 = r / S, s = r - c32*S;
    float t[8]; float sn = 0.f;
#pragma unroll
    for (int i = 0; i < 8; i++) {
        t[i] = g_p[(size_t)(b*OCH + i*32 + c32)*S + s];
        sn += t[i]*t[i];
    }
    float scale = sn/(1.f + sn) * rsqrtf(sn + 1e-12f);
#pragma unroll
    for (int i = 0; i < 8; i++)
        g_u[(size_t)idx*8 + i] = t[i]*scale;
}

// ---------------- priors ----------------
__global__ void priors_kernel(const float* __restrict__ dw, int R) {
    int r = blockIdx.x, n = blockIdx.y;
    __shared__ float w[128];
    if (threadIdx.x < 128)
        w[threadIdx.x] = dw[((size_t)n*R + r)*128 + threadIdx.x];
    __syncthreads();
    int b = threadIdx.x;
    float u[8];
#pragma unroll
    for (int i = 0; i < 8; i++) u[i] = g_u[((size_t)b*R + r)*8 + i];
    float* out = g_priors + (((size_t)n*BATCH + b)*R + r)*16;
#pragma unroll
    for (int o = 0; o < 16; o++) {
        float s = 0.f;
#pragma unroll
        for (int i = 0; i < 8; i++) s += u[i]*w[i*16 + o];
        out[o] = s;
    }
}

// ---------------- dynamic routing ----------------
__global__ void routing_kernel(int R, int br) {
    int b = blockIdx.x, n = blockIdx.y;
    extern __shared__ float sm[];
    float* P    = sm;
    float* blog = P + R*16;
    float* wred = blog + R;
    float* vv   = wred + 128;
    float* sred = vv + 16;
    float* scal = sred + 8;

    int tid = threadIdx.x;
    const float* gp = g_priors + (((size_t)n*BATCH + b)*R)*16;
    for (int i = tid; i < R*16; i += 256) P[i] = gp[i];
    for (int r = tid; r < R;    r += 256) blog[r] = 0.f;
    __syncthreads();

    for (int it = 0; it < 3; it++) {
        float mx = -1e30f;
        for (int r = tid; r < R; r += 256) mx = fmaxf(mx, blog[r]);
#pragma unroll
        for (int off = 16; off; off >>= 1)
            mx = fmaxf(mx, __shfl_xor_sync(0xffffffffu, mx, off));
        if ((tid & 31) == 0) sred[tid >> 5] = mx;
        __syncthreads();
        if (tid == 0) {
            float m = sred[0];
            for (int w2 = 1; w2 < 8; w2++) m = fmaxf(m, sred[w2]);
            scal[0] = m;
        }
        __syncthreads();
        float gmax = scal[0];
        float se = 0.f;
        for (int r = tid; r < R; r += 256) se += expf(blog[r] - gmax);
#pragma unroll
        for (int off = 16; off; off >>= 1)
            se += __shfl_xor_sync(0xffffffffu, se, off);
        if ((tid & 31) == 0) sred[tid >> 5] = se;
        __syncthreads();
        if (tid == 0) {
            float s = 0.f;
            for (int w2 = 0; w2 < 8; w2++) s += sred[w2];
            scal[1] = 1.f/s;
        }
        __syncthreads();
        float isum = scal[1];
        float acc[16];
#pragma unroll
        for (int o = 0; o < 16; o++) acc[o] = 0.f;
        for (int r = tid; r < R; r += 256) {
            float c = expf(blog[r] - gmax)*isum;
            const float* pr = P + r*16;
#pragma unroll
            for (int o = 0; o < 16; o++) acc[o] += c*pr[o];
        }
#pragma unroll
        for (int o = 0; o < 16; o++) {
            float v = acc[o];
#pragma unroll
            for (int off = 16; off; off >>= 1)
                v += __shfl_xor_sync(0xffffffffu, v, off);
            acc[o] = v;
        }
        if ((tid & 31) == 0)
#pragma unroll
            for (int o = 0; o < 16; o++) wred[(tid >> 5)*16 + o] = acc[o];
        __syncthreads();
        if (tid == 0) {
            float s16[16]; float sn = 0.f;
#pragma unroll
            for (int o = 0; o < 16; o++) {
                float s = 0.f;
                for (int w2 = 0; w2 < 8; w2++) s += wred[w2*16 + o];
                s16[o] = s; sn += s*s;
            }
            float sc = sn/(1.f + sn) * rsqrtf(sn + 1e-12f);
#pragma unroll
            for (int o = 0; o < 16; o++) vv[o] = s16[o]*sc;
        }
        __syncthreads();
        if (it < 2) {
            for (int r = tid; r < R; r += 256) {
                const float* pr = P + r*16;
                float d = 0.f;
#pragma unroll
                for (int o = 0; o < 16; o++) d += pr[o]*vv[o];
                blog[r] += d;
            }
            __syncthreads();
        }
    }
    if (tid == 0) {
        float s = 0.f;
#pragma unroll
        for (int o = 0; o < 16; o++) s += vv[o]*vv[o];
        g_len[br*BATCH*NCLS + b*NCLS + n] = sqrtf(s + 1e-12f);
    }
}

// ---------------- final ----------------
__global__ void final_kernel(float* __restrict__ out) {
    int b = blockIdx.x*blockDim.x + threadIdx.x;
    if (b >= BATCH) return;
    float l[NCLS]; float mx = -1e30f;
#pragma unroll
    for (int n = 0; n < NCLS; n++) {
        l[n] = g_len[0*BATCH*NCLS + b*NCLS + n]
             + g_len[1*BATCH*NCLS + b*NCLS + n]
             + g_len[2*BATCH*NCLS + b*NCLS + n];
        mx = fmaxf(mx, l[n]);
    }
    float s = 0.f;
#pragma unroll
    for (int n = 0; n < NCLS; n++) { l[n] = expf(l[n] - mx); s += l[n]; }
    float inv = 1.f/s;
#pragma unroll
    for (int n = 0; n < NCLS; n++) out[b*NCLS + n] = l[n]*inv;
}

// ---------------- host driver ----------------
struct BranchCfg {
    int src;
    int H, k1, H1, kp, Hp, S, R, K;
    int iw;
};

static void run_branch(const BranchCfg& c, void* const* d_in, const float* x, int br)
{
    const float* cw = (const float*)d_in[c.iw + 0];
    const float* cb = (const float*)d_in[c.iw + 1];
    const float* pw = (const float*)d_in[c.iw + 2];
    const float* pb = (const float*)d_in[c.iw + 3];
    const float* dw = (const float*)d_in[c.iw + 4];

    int HW = c.H1*c.H1;
    int totalA = BATCH*CC*HW;
    convA_kernel<<<(totalA + 255)/256, 256>>>(x, c.src, cw, cb, c.H, c.H1, c.k1);
    bn_stats_kernel<<<CC, 256>>>(HW);
    bn_apply_kernel<<<(totalA + 255)/256, 256>>>(HW);

    prep_w_kernel<<<(OCH*c.K + 255)/256, 256>>>(pw, c.K);
    prep_ktab_kernel<<<(c.K + 255)/256, 256>>>(c.K, c.kp, c.H1);

    int M = BATCH*c.S;
    im2col_kernel<<<M, 256>>>(c.S, c.Hp, c.H1, c.K);

    prim_mma_kernel<<<2*(M/128), 256, GSMEM>>>(pb, c.S, c.K);

    squash_u_kernel<<<(BATCH*c.R + 255)/256, 256>>>(c.S, c.R);

    dim3 pgrid(c.R, NCLS);
    priors_kernel<<<pgrid, 256>>>(dw, c.R);

    int smemR = (c.R*17 + 128 + 16 + 8 + 2)*(int)sizeof(float);
    dim3 rgrid(BATCH, NCLS);
    routing_kernel<<<rgrid, 256, smemR>>>(c.R, br);
}

extern "C" void kernel_launch(void* const* d_in, const int* in_sizes, int n_in,
                              void* d_out, int out_size)
{
    (void)in_sizes; (void)n_in; (void)out_size;
    const float* x = (const float*)d_in[0];
    float* out = (float*)d_out;

    cudaFuncSetAttribute(routing_kernel, cudaFuncAttributeMaxDynamicSharedMemorySize, 96*1024);
    cudaFuncSetAttribute(prim_mma_kernel, cudaFuncAttributeMaxDynamicSharedMemorySize, GSMEM);

    pool2_kernel<<<(BATCH*14*14 + 255)/256, 256>>>(x);
    pool1_kernel<<<(BATCH*7*7 + 255)/256, 256>>>();

    //                src  H  k1 H1  kp Hp  S    R      K   iw
    BranchCfg b1 = {   2,  7, 3,  5,  3, 2,  4,  128,  1152,  1 };
    BranchCfg b2 = {   1, 14, 5, 10,  5, 3,  9,  288,  3200,  6 };
    BranchCfg b3 = {   0, 28, 9, 20,  9, 6, 36, 1152, 10368, 11 };

    run_branch(b1, d_in, x, 0);
    run_branch(b2, d_in, x, 1);
    run_branch(b3, d_in, x, 2);

    final_kernel<<<1, 256>>>(out);
}

// round 4
// speedup vs baseline: 1.6639x; 1.2106x over previous
#include <cuda_runtime.h>
#include <cuda_bf16.h>
#include <math.h>
#include <stdint.h>

#define BATCH 256
#define NCLS  10
#define CC    128
#define OCH   256

// GEMM tiling
#define TSTRIDE 40                // bf16 elems per smem row (80B, 16B-aligned)
#define TILEB   (128*TSTRIDE*2)   // 10240 B per 128x32 bf16 tile
#define STAGEB  (4*TILEB)         // Ah,Al,Bh,Bl = 40960 B
#define GSMEM   (2*STAGEB)        // double buffered = 81920 B

// ---------------- static device scratch (max = branch 3 sizes) ----------------
__device__ float g_x2[BATCH*14*14];
__device__ float g_x1[BATCH*7*7];
__device__ float g_y [BATCH*CC*20*20];
__device__ float g_mean[CC];
__device__ float g_rstd[CC];
__device__ int   g_ktab[10368];                      // (channel<<20) | input offset
__device__ __nv_bfloat16 g_wh[(size_t)OCH*10368];
__device__ __nv_bfloat16 g_wl[(size_t)OCH*10368];
__device__ __nv_bfloat16 g_Ah[(size_t)9216*10368];
__device__ __nv_bfloat16 g_Al[(size_t)9216*10368];
__device__ float g_p [BATCH*36*OCH];                 // layout [m][oc]
__device__ float g_u [BATCH*1152*8];
__device__ float g_priors[(size_t)NCLS*BATCH*1152*16];
__device__ float g_len[3*BATCH*NCLS];

// ---------------- PTX helpers ----------------
__device__ __forceinline__ uint32_t smem_u32(const void* p) {
    uint32_t a;
    asm("{ .reg .u64 t; cvta.to.shared.u64 t, %1; cvt.u32.u64 %0, t; }" : "=r"(a) : "l"(p));
    return a;
}
#define CP_ASYNC16(dst, src) \
    asm volatile("cp.async.ca.shared.global [%0], [%1], 16;" :: "r"(dst), "l"(src) : "memory")
#define CP_COMMIT() asm volatile("cp.async.commit_group;" ::: "memory")
#define CP_WAIT0()  asm volatile("cp.async.wait_group 0;" ::: "memory")
#define CP_WAIT1()  asm volatile("cp.async.wait_group 1;" ::: "memory")

__device__ __forceinline__ void ldmx4(uint32_t addr, uint32_t& r0, uint32_t& r1,
                                      uint32_t& r2, uint32_t& r3) {
    asm volatile("ldmatrix.sync.aligned.m8n8.x4.shared.b16 {%0,%1,%2,%3}, [%4];"
                 : "=r"(r0), "=r"(r1), "=r"(r2), "=r"(r3) : "r"(addr));
}
__device__ __forceinline__ void mma16816(float* c, const uint32_t* a, uint32_t b0, uint32_t b1) {
    asm volatile(
        "mma.sync.aligned.m16n8k16.row.col.f32.bf16.bf16.f32 "
        "{%0,%1,%2,%3}, {%4,%5,%6,%7}, {%8,%9}, {%0,%1,%2,%3};"
        : "+f"(c[0]), "+f"(c[1]), "+f"(c[2]), "+f"(c[3])
        : "r"(a[0]), "r"(a[1]), "r"(a[2]), "r"(a[3]), "r"(b0), "r"(b1));
}

// ---------------- pooling ----------------
__global__ void pool2_kernel(const float* __restrict__ img) {
    int idx = blockIdx.x*blockDim.x + threadIdx.x;
    if (idx >= BATCH*14*14) return;
    int j = idx % 14, i = (idx/14) % 14, b = idx/196;
    const float* p = img + b*784;
    g_x2[idx] = 0.25f*(p[(2*i)*28+2*j] + p[(2*i)*28+2*j+1]
                     + p[(2*i+1)*28+2*j] + p[(2*i+1)*28+2*j+1]);
}
__global__ void pool1_kernel() {
    int idx = blockIdx.x*blockDim.x + threadIdx.x;
    if (idx >= BATCH*7*7) return;
    int j = idx % 7, i = (idx/7) % 7, b = idx/49;
    const float* p = g_x2 + b*196;
    g_x1[idx] = 0.25f*(p[(2*i)*14+2*j] + p[(2*i)*14+2*j+1]
                     + p[(2*i+1)*14+2*j] + p[(2*i+1)*14+2*j+1]);
}

// ---------------- conv stage A: smem-tiled, compile-time k ----------------
// one CTA per image. smem: input H*H + weights 128*K1*K1.
// thread handles (c, oy) pairs, computes full H1-wide output row.
template<int K1, int H, int H1>
__global__ __launch_bounds__(256) void convA_smem(const float* __restrict__ xin_ext, int src,
                                                  const float* __restrict__ w,
                                                  const float* __restrict__ bias)
{
    __shared__ float s_in[H*H];
    __shared__ float s_w[CC*K1*K1];
    int b = blockIdx.x;
    int tid = threadIdx.x;
    const float* xin = (src == 0) ? xin_ext : (src == 1 ? g_x2 : g_x1);
    const float* ip = xin + b*H*H;
    for (int i = tid; i < H*H; i += 256) s_in[i] = ip[i];
    for (int i = tid; i < CC*K1*K1; i += 256) s_w[i] = w[i];
    __syncthreads();

    for (int pair = tid; pair < CC*H1; pair += 256) {
        int c = pair & (CC-1), oy = pair >> 7;
        float bv = __ldg(&bias[c]);
        float acc[H1];
#pragma unroll
        for (int ox = 0; ox < H1; ox++) acc[ox] = bv;
        const float* wc = s_w + c*K1*K1;
#pragma unroll
        for (int ky = 0; ky < K1; ky++) {
            float row[H1 + K1 - 1];
            const float* rp = s_in + (oy + ky)*H;
#pragma unroll
            for (int x = 0; x < H1 + K1 - 1; x++) row[x] = rp[x];
#pragma unroll
            for (int kx = 0; kx < K1; kx++) {
                float wv = wc[ky*K1 + kx];
#pragma unroll
                for (int ox = 0; ox < H1; ox++)
                    acc[ox] = fmaf(wv, row[ox + kx], acc[ox]);
            }
        }
        float* op = g_y + ((size_t)(b*CC + c)*H1 + oy)*H1;
#pragma unroll
        for (int ox = 0; ox < H1; ox++) op[ox] = fmaxf(acc[ox], 0.f);
    }
}

// ---------------- batchnorm stats (apply is folded into im2col) ----------------
__global__ void bn_stats_kernel(int HW) {
    int c = blockIdx.x;
    int tid = threadIdx.x;
    int N = BATCH*HW;
    float s = 0.f, s2 = 0.f;
    for (int i = tid; i < N; i += blockDim.x) {
        int b = i / HW, hw = i - b*HW;
        float v = g_y[(b*CC + c)*HW + hw];
        s += v; s2 += v*v;
    }
    __shared__ float rs[256], rq[256];
    rs[tid] = s; rq[tid] = s2;
    __syncthreads();
    for (int off = 128; off; off >>= 1) {
        if (tid < off) { rs[tid] += rs[tid+off]; rq[tid] += rq[tid+off]; }
        __syncthreads();
    }
    if (tid == 0) {
        float m = rs[0] / (float)N;
        float var = rq[0] / (float)N - m*m;
        g_mean[c] = m;
        g_rstd[c] = rsqrtf(var + 1e-5f);
    }
}

// ---------------- prep: split weights, packed ktab, fused-BN im2col ----------------
__global__ void prep_w_kernel(const float* __restrict__ pw, int K) {
    int idx = blockIdx.x*blockDim.x + threadIdx.x;
    if (idx >= OCH*K) return;
    float v = pw[idx];
    __nv_bfloat16 h = __float2bfloat16(v);
    g_wh[idx] = h;
    g_wl[idx] = __float2bfloat16(v - __bfloat162float(h));
}
__global__ void prep_ktab_kernel(int K, int kp, int H1) {
    int kidx = blockIdx.x*blockDim.x + threadIdx.x;
    if (kidx >= K) return;
    int kk2 = kp*kp;
    int ic = kidx / kk2;
    int rem = kidx - ic*kk2;
    int off = ic*H1*H1 + (rem/kp)*H1 + (rem % kp);
    g_ktab[kidx] = (ic << 20) | off;
}
__global__ void im2col_kernel(int S, int Hp, int H1, int K) {
    int m = blockIdx.x;
    int b = m / S, s = m - b*S;
    int oy = s / Hp, ox = s - oy*Hp;
    const float* src = g_y + (b*CC)*H1*H1 + (oy*2)*H1 + ox*2;
    size_t base = (size_t)m*K;
    __nv_bfloat162* dh = reinterpret_cast<__nv_bfloat162*>(g_Ah + base);
    __nv_bfloat162* dl = reinterpret_cast<__nv_bfloat162*>(g_Al + base);
    for (int k2 = threadIdx.x; k2*2 < K; k2 += blockDim.x) {
        int t0 = g_ktab[k2*2], t1 = g_ktab[k2*2 + 1];
        int c0 = t0 >> 20, c1 = t1 >> 20;
        float v0 = (src[t0 & 0xFFFFF] - g_mean[c0]) * g_rstd[c0];
        float v1 = (src[t1 & 0xFFFFF] - g_mean[c1]) * g_rstd[c1];
        __nv_bfloat16 h0 = __float2bfloat16(v0);
        __nv_bfloat16 h1 = __float2bfloat16(v1);
        dh[k2] = __halves2bfloat162(h0, h1);
        dl[k2] = __halves2bfloat162(__float2bfloat16(v0 - __bfloat162float(h0)),
                                    __float2bfloat16(v1 - __bfloat162float(h1)));
    }
}

// ---------------- prim conv GEMM: mma.sync bf16 split, 128x128 tile ----------------
__device__ __forceinline__ void load_stage(uint32_t sb, int buf,
                                           int m0, int n0, int kc, int K, int tid)
{
    uint32_t dst0 = sb + buf*STAGEB;
#pragma unroll
    for (int i = 0; i < 8; i++) {
        int q = tid + i*256;
        int mat = q >> 9;              // 0:Ah 1:Al 2:Bh 3:Bl
        int w = q & 511;
        int row = w >> 2;
        int ch  = w & 3;
        const __nv_bfloat16* gsrc;
        if      (mat == 0) gsrc = g_Ah + (size_t)(m0 + row)*K + kc + ch*8;
        else if (mat == 1) gsrc = g_Al + (size_t)(m0 + row)*K + kc + ch*8;
        else if (mat == 2) gsrc = g_wh + (size_t)(n0 + row)*K + kc + ch*8;
        else               gsrc = g_wl + (size_t)(n0 + row)*K + kc + ch*8;
        uint32_t dst = dst0 + mat*TILEB + row*(TSTRIDE*2) + ch*16;
        CP_ASYNC16(dst, gsrc);
    }
}

__global__ __launch_bounds__(256) void prim_mma_kernel(const float* __restrict__ pb, int S, int K)
{
    extern __shared__ char smem[];
    uint32_t sb = smem_u32(smem);
    int tid = threadIdx.x, wid = tid >> 5, lane = tid & 31;
    int n0 = (blockIdx.x & 1) << 7;
    int m0 = (int)(blockIdx.x >> 1) << 7;

    int wm = (wid & 3) << 5;   // warp m-origin (32-row slab)
    int wn = (wid >> 2) << 6;  // warp n-origin (64-col slab)

    float acc[2][8][4];
#pragma unroll
    for (int mt = 0; mt < 2; mt++)
#pragma unroll
        for (int nb = 0; nb < 8; nb++)
#pragma unroll
            for (int j = 0; j < 4; j++) acc[mt][nb][j] = 0.f;

    int nch = K >> 5;
    load_stage(sb, 0, m0, n0, 0, K, tid);
    CP_COMMIT();

    uint32_t aLaneOff = (uint32_t)((lane & 15)*(TSTRIDE*2) + (lane >> 4)*16);
    uint32_t bLaneOff = (uint32_t)((((lane >> 3) & 3)*8 + (lane & 7))*(TSTRIDE*2));

    for (int c = 0; c < nch; c++) {
        int buf = c & 1;
        if (c + 1 < nch) {
            load_stage(sb, buf ^ 1, m0, n0, (c + 1) << 5, K, tid);
            CP_COMMIT();
            CP_WAIT1();
        } else {
            CP_WAIT0();
        }
        __syncthreads();

        uint32_t st = sb + buf*STAGEB;
#pragma unroll
        for (int pass = 0; pass < 3; pass++) {
            uint32_t aBase = st + ((pass == 2) ? TILEB : 0);
            uint32_t bBase = st + ((pass == 1) ? 3*TILEB : 2*TILEB);
#pragma unroll
            for (int kk = 0; kk < 2; kk++) {
                uint32_t a[2][4];
#pragma unroll
                for (int mt = 0; mt < 2; mt++)
                    ldmx4(aBase + (wm + mt*16)*(TSTRIDE*2) + kk*32 + aLaneOff,
                          a[mt][0], a[mt][1], a[mt][2], a[mt][3]);
                uint32_t b[8][2];
#pragma unroll
                for (int g = 0; g < 2; g++)
#pragma unroll
                    for (int kh = 0; kh < 2; kh++) {
                        uint32_t r0, r1, r2, r3;
                        ldmx4(bBase + (wn + g*32)*(TSTRIDE*2) + kk*32 + kh*16 + bLaneOff,
                              r0, r1, r2, r3);
                        b[g*4+0][kh] = r0; b[g*4+1][kh] = r1;
                        b[g*4+2][kh] = r2; b[g*4+3][kh] = r3;
                    }
#pragma unroll
                for (int mt = 0; mt < 2; mt++)
#pragma unroll
                    for (int nb = 0; nb < 8; nb++)
                        mma16816(acc[mt][nb], a[mt], b[nb][0], b[nb][1]);
            }
        }
        __syncthreads();
    }

    // epilogue: g_p layout [m][oc], coalesced 8B pairs
    int gr = lane >> 2, tc = lane & 3;
#pragma unroll
    for (int mt = 0; mt < 2; mt++) {
        int mA = m0 + wm + mt*16 + gr;
        int mB = mA + 8;
#pragma unroll
        for (int nb = 0; nb < 8; nb++) {
            int oc = n0 + wn + nb*8 + tc*2;
            float bias0 = pb[oc], bias1 = pb[oc+1];
            float2 vA = make_float2(acc[mt][nb][0] + bias0, acc[mt][nb][1] + bias1);
            float2 vB = make_float2(acc[mt][nb][2] + bias0, acc[mt][nb][3] + bias1);
            *reinterpret_cast<float2*>(g_p + (size_t)mA*OCH + oc) = vA;
            *reinterpret_cast<float2*>(g_p + (size_t)mB*OCH + oc) = vB;
        }
    }
}

// ---------------- squash primary capsules ----------------
__global__ void squash_u_kernel(int S, int R) {
    int idx = blockIdx.x*blockDim.x + threadIdx.x;
    if (idx >= BATCH*R) return;
    int r = idx % R, b = idx / R;
    int c32 = r / S, s = r - c32*S;
    const float* pp = g_p + (size_t)(b*S + s)*OCH + c32;
    float t[8]; float sn = 0.f;
#pragma unroll
    for (int i = 0; i < 8; i++) {
        t[i] = pp[i*32];
        sn += t[i]*t[i];
    }
    float scale = sn/(1.f + sn) * rsqrtf(sn + 1e-12f);
#pragma unroll
    for (int i = 0; i < 8; i++)
        g_u[(size_t)idx*8 + i] = t[i]*scale;
}

// ---------------- priors ----------------
__global__ void priors_kernel(const float* __restrict__ dw, int R) {
    int r = blockIdx.x, n = blockIdx.y;
    __shared__ float w[128];
    if (threadIdx.x < 128)
        w[threadIdx.x] = dw[((size_t)n*R + r)*128 + threadIdx.x];
    __syncthreads();
    int b = threadIdx.x;
    float u[8];
#pragma unroll
    for (int i = 0; i < 8; i++) u[i] = g_u[((size_t)b*R + r)*8 + i];
    float* out = g_priors + (((size_t)n*BATCH + b)*R + r)*16;
#pragma unroll
    for (int o = 0; o < 16; o++) {
        float s = 0.f;
#pragma unroll
        for (int i = 0; i < 8; i++) s += u[i]*w[i*16 + o];
        out[o] = s;
    }
}

// ---------------- dynamic routing ----------------
__global__ void routing_kernel(int R, int br) {
    int b = blockIdx.x, n = blockIdx.y;
    extern __shared__ float sm[];
    float* P    = sm;
    float* blog = P + R*16;
    float* wred = blog + R;
    float* vv   = wred + 128;
    float* sred = vv + 16;
    float* scal = sred + 8;

    int tid = threadIdx.x;
    const float* gp = g_priors + (((size_t)n*BATCH + b)*R)*16;
    for (int i = tid; i < R*16; i += 256) P[i] = gp[i];
    for (int r = tid; r < R;    r += 256) blog[r] = 0.f;
    __syncthreads();

    for (int it = 0; it < 3; it++) {
        float mx = -1e30f;
        for (int r = tid; r < R; r += 256) mx = fmaxf(mx, blog[r]);
#pragma unroll
        for (int off = 16; off; off >>= 1)
            mx = fmaxf(mx, __shfl_xor_sync(0xffffffffu, mx, off));
        if ((tid & 31) == 0) sred[tid >> 5] = mx;
        __syncthreads();
        if (tid == 0) {
            float m = sred[0];
            for (int w2 = 1; w2 < 8; w2++) m = fmaxf(m, sred[w2]);
            scal[0] = m;
        }
        __syncthreads();
        float gmax = scal[0];
        float se = 0.f;
        for (int r = tid; r < R; r += 256) se += expf(blog[r] - gmax);
#pragma unroll
        for (int off = 16; off; off >>= 1)
            se += __shfl_xor_sync(0xffffffffu, se, off);
        if ((tid & 31) == 0) sred[tid >> 5] = se;
        __syncthreads();
        if (tid == 0) {
            float s = 0.f;
            for (int w2 = 0; w2 < 8; w2++) s += sred[w2];
            scal[1] = 1.f/s;
        }
        __syncthreads();
        float isum = scal[1];
        float acc[16];
#pragma unroll
        for (int o = 0; o < 16; o++) acc[o] = 0.f;
        for (int r = tid; r < R; r += 256) {
            float c = expf(blog[r] - gmax)*isum;
            const float* pr = P + r*16;
#pragma unroll
            for (int o = 0; o < 16; o++) acc[o] += c*pr[o];
        }
#pragma unroll
        for (int o = 0; o < 16; o++) {
            float v = acc[o];
#pragma unroll
            for (int off = 16; off; off >>= 1)
                v += __shfl_xor_sync(0xffffffffu, v, off);
            acc[o] = v;
        }
        if ((tid & 31) == 0)
#pragma unroll
            for (int o = 0; o < 16; o++) wred[(tid >> 5)*16 + o] = acc[o];
        __syncthreads();
        if (tid == 0) {
            float s16[16]; float sn = 0.f;
#pragma unroll
            for (int o = 0; o < 16; o++) {
                float s = 0.f;
                for (int w2 = 0; w2 < 8; w2++) s += wred[w2*16 + o];
                s16[o] = s; sn += s*s;
            }
            float sc = sn/(1.f + sn) * rsqrtf(sn + 1e-12f);
#pragma unroll
            for (int o = 0; o < 16; o++) vv[o] = s16[o]*sc;
        }
        __syncthreads();
        if (it < 2) {
            for (int r = tid; r < R; r += 256) {
                const float* pr = P + r*16;
                float d = 0.f;
#pragma unroll
                for (int o = 0; o < 16; o++) d += pr[o]*vv[o];
                blog[r] += d;
            }
            __syncthreads();
        }
    }
    if (tid == 0) {
        float s = 0.f;
#pragma unroll
        for (int o = 0; o < 16; o++) s += vv[o]*vv[o];
        g_len[br*BATCH*NCLS + b*NCLS + n] = sqrtf(s + 1e-12f);
    }
}

// ---------------- final ----------------
__global__ void final_kernel(float* __restrict__ out) {
    int b = blockIdx.x*blockDim.x + threadIdx.x;
    if (b >= BATCH) return;
    float l[NCLS]; float mx = -1e30f;
#pragma unroll
    for (int n = 0; n < NCLS; n++) {
        l[n] = g_len[0*BATCH*NCLS + b*NCLS + n]
             + g_len[1*BATCH*NCLS + b*NCLS + n]
             + g_len[2*BATCH*NCLS + b*NCLS + n];
        mx = fmaxf(mx, l[n]);
    }
    float s = 0.f;
#pragma unroll
    for (int n = 0; n < NCLS; n++) { l[n] = expf(l[n] - mx); s += l[n]; }
    float inv = 1.f/s;
#pragma unroll
    for (int n = 0; n < NCLS; n++) out[b*NCLS + n] = l[n]*inv;
}

// ---------------- host driver ----------------
struct BranchCfg {
    int src;
    int H, k1, H1, kp, Hp, S, R, K;
    int iw;
};

static void run_branch(const BranchCfg& c, void* const* d_in, const float* x, int br)
{
    const float* cw = (const float*)d_in[c.iw + 0];
    const float* cb = (const float*)d_in[c.iw + 1];
    const float* pw = (const float*)d_in[c.iw + 2];
    const float* pb = (const float*)d_in[c.iw + 3];
    const float* dw = (const float*)d_in[c.iw + 4];

    int HW = c.H1*c.H1;
    if (c.k1 == 3)      convA_smem<3, 7, 5 ><<<BATCH, 256>>>(x, c.src, cw, cb);
    else if (c.k1 == 5) convA_smem<5, 14, 10><<<BATCH, 256>>>(x, c.src, cw, cb);
    else                convA_smem<9, 28, 20><<<BATCH, 256>>>(x, c.src, cw, cb);
    bn_stats_kernel<<<CC, 256>>>(HW);

    prep_w_kernel<<<(OCH*c.K + 255)/256, 256>>>(pw, c.K);
    prep_ktab_kernel<<<(c.K + 255)/256, 256>>>(c.K, c.kp, c.H1);

    int M = BATCH*c.S;
    im2col_kernel<<<M, 256>>>(c.S, c.Hp, c.H1, c.K);

    prim_mma_kernel<<<2*(M/128), 256, GSMEM>>>(pb, c.S, c.K);

    squash_u_kernel<<<(BATCH*c.R + 255)/256, 256>>>(c.S, c.R);

    dim3 pgrid(c.R, NCLS);
    priors_kernel<<<pgrid, 256>>>(dw, c.R);

    int smemR = (c.R*17 + 128 + 16 + 8 + 2)*(int)sizeof(float);
    dim3 rgrid(BATCH, NCLS);
    routing_kernel<<<rgrid, 256, smemR>>>(c.R, br);
}

extern "C" void kernel_launch(void* const* d_in, const int* in_sizes, int n_in,
                              void* d_out, int out_size)
{
    (void)in_sizes; (void)n_in; (void)out_size;
    const float* x = (const float*)d_in[0];
    float* out = (float*)d_out;

    cudaFuncSetAttribute(routing_kernel, cudaFuncAttributeMaxDynamicSharedMemorySize, 96*1024);
    cudaFuncSetAttribute(prim_mma_kernel, cudaFuncAttributeMaxDynamicSharedMemorySize, GSMEM);

    pool2_kernel<<<(BATCH*14*14 + 255)/256, 256>>>(x);
    pool1_kernel<<<(BATCH*7*7 + 255)/256, 256>>>();

    //                src  H  k1 H1  kp Hp  S    R      K   iw
    BranchCfg b1 = {   2,  7, 3,  5,  3, 2,  4,  128,  1152,  1 };
    BranchCfg b2 = {   1, 14, 5, 10,  5, 3,  9,  288,  3200,  6 };
    BranchCfg b3 = {   0, 28, 9, 20,  9, 6, 36, 1152, 10368, 11 };

    run_branch(b1, d_in, x, 0);
    run_branch(b2, d_in, x, 1);
    run_branch(b3, d_in, x, 2);

    final_kernel<<<1, 256>>>(out);
}

// round 5
// speedup vs baseline: 1.9243x; 1.1565x over previous
#include <cuda_runtime.h>
#include <cuda_bf16.h>
#include <math.h>
#include <stdint.h>

#define BATCH 256
#define NCLS  10
#define CC    128
#define OCH   256

// GEMM tiling
#define TSTRIDE 40                // bf16 elems per smem row (80B, 16B-aligned)
#define TILEB   (128*TSTRIDE*2)   // 10240 B per 128x32 bf16 tile
#define STAGEB  (4*TILEB)         // Ah,Al,Bh,Bl = 40960 B
#define GSMEM   (2*STAGEB)        // double buffered = 81920 B

// ---------------- static device scratch, per-branch offsets ----------------
__device__ float g_x2[BATCH*14*14];
__device__ float g_x1[BATCH*7*7];
__device__ float g_y [17203200];            // b1:819200 b2:3276800 b3:13107200
__device__ float g_mean[3*CC];
__device__ float g_rstd[3*CC];
__device__ int   g_ktab[14720];             // b1:1152 b2:3200 b3:10368
__device__ __nv_bfloat16 g_wh[3768320];     // OCH*K per branch
__device__ __nv_bfloat16 g_wl[3768320];
__device__ __nv_bfloat16 g_Ah[104103936];   // M*K per branch
__device__ __nv_bfloat16 g_Al[104103936];
__device__ float g_p [3211264];             // [m][oc] per branch
__device__ float g_u [3211264];
__device__ float g_priors[64225280];
__device__ float g_len[3*BATCH*NCLS];

// ---------------- PTX helpers ----------------
__device__ __forceinline__ uint32_t smem_u32(const void* p) {
    uint32_t a;
    asm("{ .reg .u64 t; cvta.to.shared.u64 t, %1; cvt.u32.u64 %0, t; }" : "=r"(a) : "l"(p));
    return a;
}
#define CP_ASYNC16(dst, src) \
    asm volatile("cp.async.ca.shared.global [%0], [%1], 16;" :: "r"(dst), "l"(src) : "memory")
#define CP_COMMIT() asm volatile("cp.async.commit_group;" ::: "memory")
#define CP_WAIT0()  asm volatile("cp.async.wait_group 0;" ::: "memory")
#define CP_WAIT1()  asm volatile("cp.async.wait_group 1;" ::: "memory")

__device__ __forceinline__ void ldmx4(uint32_t addr, uint32_t& r0, uint32_t& r1,
                                      uint32_t& r2, uint32_t& r3) {
    asm volatile("ldmatrix.sync.aligned.m8n8.x4.shared.b16 {%0,%1,%2,%3}, [%4];"
                 : "=r"(r0), "=r"(r1), "=r"(r2), "=r"(r3) : "r"(addr));
}
__device__ __forceinline__ void mma16816(float* c, const uint32_t* a, uint32_t b0, uint32_t b1) {
    asm volatile(
        "mma.sync.aligned.m16n8k16.row.col.f32.bf16.bf16.f32 "
        "{%0,%1,%2,%3}, {%4,%5,%6,%7}, {%8,%9}, {%0,%1,%2,%3};"
        : "+f"(c[0]), "+f"(c[1]), "+f"(c[2]), "+f"(c[3])
        : "r"(a[0]), "r"(a[1]), "r"(a[2]), "r"(a[3]), "r"(b0), "r"(b1));
}

// ---------------- pooling ----------------
__global__ void pool2_kernel(const float* __restrict__ img) {
    int idx = blockIdx.x*blockDim.x + threadIdx.x;
    if (idx >= BATCH*14*14) return;
    int j = idx % 14, i = (idx/14) % 14, b = idx/196;
    const float* p = img + b*784;
    g_x2[idx] = 0.25f*(p[(2*i)*28+2*j] + p[(2*i)*28+2*j+1]
                     + p[(2*i+1)*28+2*j] + p[(2*i+1)*28+2*j+1]);
}
__global__ void pool1_kernel() {
    int idx = blockIdx.x*blockDim.x + threadIdx.x;
    if (idx >= BATCH*7*7) return;
    int j = idx % 7, i = (idx/7) % 7, b = idx/49;
    const float* p = g_x2 + b*196;
    g_x1[idx] = 0.25f*(p[(2*i)*14+2*j] + p[(2*i)*14+2*j+1]
                     + p[(2*i+1)*14+2*j] + p[(2*i+1)*14+2*j+1]);
}

// ---------------- conv stage A: smem-tiled, compile-time k ----------------
template<int K1, int H, int H1>
__global__ __launch_bounds__(256) void convA_smem(const float* __restrict__ xin_ext, int src,
                                                  const float* __restrict__ w,
                                                  const float* __restrict__ bias,
                                                  size_t yo)
{
    __shared__ float s_in[H*H];
    __shared__ float s_w[CC*K1*K1];
    int b = blockIdx.x;
    int tid = threadIdx.x;
    const float* xin = (src == 0) ? xin_ext : (src == 1 ? g_x2 : g_x1);
    const float* ip = xin + b*H*H;
    for (int i = tid; i < H*H; i += 256) s_in[i] = ip[i];
    for (int i = tid; i < CC*K1*K1; i += 256) s_w[i] = w[i];
    __syncthreads();

    for (int pair = tid; pair < CC*H1; pair += 256) {
        int c = pair & (CC-1), oy = pair >> 7;
        float bv = __ldg(&bias[c]);
        float acc[H1];
#pragma unroll
        for (int ox = 0; ox < H1; ox++) acc[ox] = bv;
        const float* wc = s_w + c*K1*K1;
#pragma unroll
        for (int ky = 0; ky < K1; ky++) {
            float row[H1 + K1 - 1];
            const float* rp = s_in + (oy + ky)*H;
#pragma unroll
            for (int x = 0; x < H1 + K1 - 1; x++) row[x] = rp[x];
#pragma unroll
            for (int kx = 0; kx < K1; kx++) {
                float wv = wc[ky*K1 + kx];
#pragma unroll
                for (int ox = 0; ox < H1; ox++)
                    acc[ox] = fmaf(wv, row[ox + kx], acc[ox]);
            }
        }
        float* op = g_y + yo + ((size_t)(b*CC + c)*H1 + oy)*H1;
#pragma unroll
        for (int ox = 0; ox < H1; ox++) op[ox] = fmaxf(acc[ox], 0.f);
    }
}

// ---------------- batchnorm stats (apply folded into im2col) ----------------
__global__ void bn_stats_kernel(int HW, size_t yo, int br) {
    int c = blockIdx.x;
    int tid = threadIdx.x;
    int N = BATCH*HW;
    float s = 0.f, s2 = 0.f;
    const float* yb = g_y + yo;
    for (int i = tid; i < N; i += blockDim.x) {
        int b = i / HW, hw = i - b*HW;
        float v = yb[(size_t)(b*CC + c)*HW + hw];
        s += v; s2 += v*v;
    }
    __shared__ float rs[256], rq[256];
    rs[tid] = s; rq[tid] = s2;
    __syncthreads();
    for (int off = 128; off; off >>= 1) {
        if (tid < off) { rs[tid] += rs[tid+off]; rq[tid] += rq[tid+off]; }
        __syncthreads();
    }
    if (tid == 0) {
        float m = rs[0] / (float)N;
        float var = rq[0] / (float)N - m*m;
        g_mean[br*CC + c] = m;
        g_rstd[br*CC + c] = rsqrtf(var + 1e-5f);
    }
}

// ---------------- prep ----------------
__global__ void prep_w_kernel(const float* __restrict__ pw, int K, size_t wo) {
    int idx = blockIdx.x*blockDim.x + threadIdx.x;
    if (idx >= OCH*K) return;
    float v = pw[idx];
    __nv_bfloat16 h = __float2bfloat16(v);
    g_wh[wo + idx] = h;
    g_wl[wo + idx] = __float2bfloat16(v - __bfloat162float(h));
}
__global__ void prep_ktab_kernel(int K, int kp, int H1, size_t ko) {
    int kidx = blockIdx.x*blockDim.x + threadIdx.x;
    if (kidx >= K) return;
    int kk2 = kp*kp;
    int ic = kidx / kk2;
    int rem = kidx - ic*kk2;
    int off = ic*H1*H1 + (rem/kp)*H1 + (rem % kp);
    g_ktab[ko + kidx] = (ic << 20) | off;
}
__global__ void im2col_kernel(int S, int Hp, int H1, int K,
                              size_t yo, size_t ko, size_t ao, int br) {
    int m = blockIdx.x;
    int b = m / S, s = m - b*S;
    int oy = s / Hp, ox = s - oy*Hp;
    const float* src = g_y + yo + (size_t)(b*CC)*H1*H1 + (oy*2)*H1 + ox*2;
    const int* kt = g_ktab + ko;
    const float* mean = g_mean + br*CC;
    const float* rstd = g_rstd + br*CC;
    size_t base = ao + (size_t)m*K;
    __nv_bfloat162* dh = reinterpret_cast<__nv_bfloat162*>(g_Ah + base);
    __nv_bfloat162* dl = reinterpret_cast<__nv_bfloat162*>(g_Al + base);
    for (int k2 = threadIdx.x; k2*2 < K; k2 += blockDim.x) {
        int t0 = kt[k2*2], t1 = kt[k2*2 + 1];
        int c0 = t0 >> 20, c1 = t1 >> 20;
        float v0 = (src[t0 & 0xFFFFF] - mean[c0]) * rstd[c0];
        float v1 = (src[t1 & 0xFFFFF] - mean[c1]) * rstd[c1];
        __nv_bfloat16 h0 = __float2bfloat16(v0);
        __nv_bfloat16 h1 = __float2bfloat16(v1);
        dh[k2] = __halves2bfloat162(h0, h1);
        dl[k2] = __halves2bfloat162(__float2bfloat16(v0 - __bfloat162float(h0)),
                                    __float2bfloat16(v1 - __bfloat162float(h1)));
    }
}

// ---------------- prim conv GEMM: mma.sync bf16 split, 128x128 tile ----------------
__device__ __forceinline__ void load_stage(uint32_t sb, int buf,
                                           int m0, int n0, int kc, int K,
                                           size_t ao, size_t wo, int tid)
{
    uint32_t dst0 = sb + buf*STAGEB;
#pragma unroll
    for (int i = 0; i < 8; i++) {
        int q = tid + i*256;
        int mat = q >> 9;              // 0:Ah 1:Al 2:Bh 3:Bl
        int w = q & 511;
        int row = w >> 2;
        int ch  = w & 3;
        const __nv_bfloat16* gsrc;
        if      (mat == 0) gsrc = g_Ah + ao + (size_t)(m0 + row)*K + kc + ch*8;
        else if (mat == 1) gsrc = g_Al + ao + (size_t)(m0 + row)*K + kc + ch*8;
        else if (mat == 2) gsrc = g_wh + wo + (size_t)(n0 + row)*K + kc + ch*8;
        else               gsrc = g_wl + wo + (size_t)(n0 + row)*K + kc + ch*8;
        uint32_t dst = dst0 + mat*TILEB + row*(TSTRIDE*2) + ch*16;
        CP_ASYNC16(dst, gsrc);
    }
}

__global__ __launch_bounds__(256) void prim_mma_kernel(const float* __restrict__ pb,
                                                       int S, int K,
                                                       size_t ao, size_t wo, size_t po)
{
    extern __shared__ char smem[];
    uint32_t sb = smem_u32(smem);
    int tid = threadIdx.x, wid = tid >> 5, lane = tid & 31;
    int n0 = (blockIdx.x & 1) << 7;
    int m0 = (int)(blockIdx.x >> 1) << 7;

    int wm = (wid & 3) << 5;   // warp m-origin (32-row slab)
    int wn = (wid >> 2) << 6;  // warp n-origin (64-col slab)

    float acc[2][8][4];
#pragma unroll
    for (int mt = 0; mt < 2; mt++)
#pragma unroll
        for (int nb = 0; nb < 8; nb++)
#pragma unroll
            for (int j = 0; j < 4; j++) acc[mt][nb][j] = 0.f;

    int nch = K >> 5;
    load_stage(sb, 0, m0, n0, 0, K, ao, wo, tid);
    CP_COMMIT();

    uint32_t aLaneOff = (uint32_t)((lane & 15)*(TSTRIDE*2) + (lane >> 4)*16);
    uint32_t bLaneOff = (uint32_t)((((lane >> 3) & 3)*8 + (lane & 7))*(TSTRIDE*2));

    for (int c = 0; c < nch; c++) {
        int buf = c & 1;
        if (c + 1 < nch) {
            load_stage(sb, buf ^ 1, m0, n0, (c + 1) << 5, K, ao, wo, tid);
            CP_COMMIT();
            CP_WAIT1();
        } else {
            CP_WAIT0();
        }
        __syncthreads();

        uint32_t st = sb + buf*STAGEB;
#pragma unroll
        for (int kk = 0; kk < 2; kk++) {
            uint32_t ah[2][4], al[2][4];
#pragma unroll
            for (int mt = 0; mt < 2; mt++)
                ldmx4(st + (wm + mt*16)*(TSTRIDE*2) + kk*32 + aLaneOff,
                      ah[mt][0], ah[mt][1], ah[mt][2], ah[mt][3]);
            uint32_t bh[8][2], bl[8][2];
#pragma unroll
            for (int g = 0; g < 2; g++)
#pragma unroll
                for (int kh = 0; kh < 2; kh++) {
                    uint32_t r0, r1, r2, r3;
                    ldmx4(st + 2*TILEB + (wn + g*32)*(TSTRIDE*2) + kk*32 + kh*16 + bLaneOff,
                          r0, r1, r2, r3);
                    bh[g*4+0][kh] = r0; bh[g*4+1][kh] = r1;
                    bh[g*4+2][kh] = r2; bh[g*4+3][kh] = r3;
                    ldmx4(st + 3*TILEB + (wn + g*32)*(TSTRIDE*2) + kk*32 + kh*16 + bLaneOff,
                          r0, r1, r2, r3);
                    bl[g*4+0][kh] = r0; bl[g*4+1][kh] = r1;
                    bl[g*4+2][kh] = r2; bl[g*4+3][kh] = r3;
                }
#pragma unroll
            for (int mt = 0; mt < 2; mt++)
#pragma unroll
                for (int nb = 0; nb < 8; nb++)
                    mma16816(acc[mt][nb], ah[mt], bh[nb][0], bh[nb][1]);
#pragma unroll
            for (int mt = 0; mt < 2; mt++)
#pragma unroll
                for (int nb = 0; nb < 8; nb++)
                    mma16816(acc[mt][nb], ah[mt], bl[nb][0], bl[nb][1]);
#pragma unroll
            for (int mt = 0; mt < 2; mt++)
                ldmx4(st + TILEB + (wm + mt*16)*(TSTRIDE*2) + kk*32 + aLaneOff,
                      al[mt][0], al[mt][1], al[mt][2], al[mt][3]);
#pragma unroll
            for (int mt = 0; mt < 2; mt++)
#pragma unroll
                for (int nb = 0; nb < 8; nb++)
                    mma16816(acc[mt][nb], al[mt], bh[nb][0], bh[nb][1]);
        }
        __syncthreads();
    }

    // epilogue: g_p layout [m][oc], coalesced 8B pairs
    int gr = lane >> 2, tc = lane & 3;
    float* gp = g_p + po;
#pragma unroll
    for (int mt = 0; mt < 2; mt++) {
        int mA = m0 + wm + mt*16 + gr;
        int mB = mA + 8;
#pragma unroll
        for (int nb = 0; nb < 8; nb++) {
            int oc = n0 + wn + nb*8 + tc*2;
            float bias0 = pb[oc], bias1 = pb[oc+1];
            float2 vA = make_float2(acc[mt][nb][0] + bias0, acc[mt][nb][1] + bias1);
            float2 vB = make_float2(acc[mt][nb][2] + bias0, acc[mt][nb][3] + bias1);
            *reinterpret_cast<float2*>(gp + (size_t)mA*OCH + oc) = vA;
            *reinterpret_cast<float2*>(gp + (size_t)mB*OCH + oc) = vB;
        }
    }
}

// ---------------- squash primary capsules ----------------
__global__ void squash_u_kernel(int S, int R, size_t po, size_t uo) {
    int idx = blockIdx.x*blockDim.x + threadIdx.x;
    if (idx >= BATCH*R) return;
    int r = idx % R, b = idx / R;
    int c32 = r / S, s = r - c32*S;
    const float* pp = g_p + po + (size_t)(b*S + s)*OCH + c32;
    float t[8]; float sn = 0.f;
#pragma unroll
    for (int i = 0; i < 8; i++) {
        t[i] = pp[i*32];
        sn += t[i]*t[i];
    }
    float scale = sn/(1.f + sn) * rsqrtf(sn + 1e-12f);
    float* up = g_u + uo + (size_t)idx*8;
#pragma unroll
    for (int i = 0; i < 8; i++)
        up[i] = t[i]*scale;
}

// ---------------- priors ----------------
__global__ void priors_kernel(const float* __restrict__ dw, int R, size_t uo, size_t pro) {
    int r = blockIdx.x, n = blockIdx.y;
    __shared__ float w[128];
    if (threadIdx.x < 128)
        w[threadIdx.x] = dw[((size_t)n*R + r)*128 + threadIdx.x];
    __syncthreads();
    int b = threadIdx.x;
    float u[8];
    const float* up = g_u + uo + ((size_t)b*R + r)*8;
#pragma unroll
    for (int i = 0; i < 8; i++) u[i] = up[i];
    float* out = g_priors + pro + (((size_t)n*BATCH + b)*R + r)*16;
#pragma unroll
    for (int o = 0; o < 16; o++) {
        float s = 0.f;
#pragma unroll
        for (int i = 0; i < 8; i++) s += u[i]*w[i*16 + o];
        out[o] = s;
    }
}

// ---------------- dynamic routing ----------------
__global__ void routing_kernel(int R, int br, size_t pro) {
    int b = blockIdx.x, n = blockIdx.y;
    extern __shared__ float sm[];
    float* P    = sm;
    float* blog = P + R*16;
    float* wred = blog + R;
    float* vv   = wred + 128;
    float* sred = vv + 16;
    float* scal = sred + 8;

    int tid = threadIdx.x;
    const float* gp = g_priors + pro + (((size_t)n*BATCH + b)*R)*16;
    for (int i = tid; i < R*16; i += 256) P[i] = gp[i];
    for (int r = tid; r < R;    r += 256) blog[r] = 0.f;
    __syncthreads();

    for (int it = 0; it < 3; it++) {
        float mx = -1e30f;
        for (int r = tid; r < R; r += 256) mx = fmaxf(mx, blog[r]);
#pragma unroll
        for (int off = 16; off; off >>= 1)
            mx = fmaxf(mx, __shfl_xor_sync(0xffffffffu, mx, off));
        if ((tid & 31) == 0) sred[tid >> 5] = mx;
        __syncthreads();
        if (tid == 0) {
            float m = sred[0];
            for (int w2 = 1; w2 < 8; w2++) m = fmaxf(m, sred[w2]);
            scal[0] = m;
        }
        __syncthreads();
        float gmax = scal[0];
        float se = 0.f;
        for (int r = tid; r < R; r += 256) se += expf(blog[r] - gmax);
#pragma unroll
        for (int off = 16; off; off >>= 1)
            se += __shfl_xor_sync(0xffffffffu, se, off);
        if ((tid & 31) == 0) sred[tid >> 5] = se;
        __syncthreads();
        if (tid == 0) {
            float s = 0.f;
            for (int w2 = 0; w2 < 8; w2++) s += sred[w2];
            scal[1] = 1.f/s;
        }
        __syncthreads();
        float isum = scal[1];
        float acc[16];
#pragma unroll
        for (int o = 0; o < 16; o++) acc[o] = 0.f;
        for (int r = tid; r < R; r += 256) {
            float c = expf(blog[r] - gmax)*isum;
            const float* pr = P + r*16;
#pragma unroll
            for (int o = 0; o < 16; o++) acc[o] += c*pr[o];
        }
#pragma unroll
        for (int o = 0; o < 16; o++) {
            float v = acc[o];
#pragma unroll
            for (int off = 16; off; off >>= 1)
                v += __shfl_xor_sync(0xffffffffu, v, off);
            acc[o] = v;
        }
        if ((tid & 31) == 0)
#pragma unroll
            for (int o = 0; o < 16; o++) wred[(tid >> 5)*16 + o] = acc[o];
        __syncthreads();
        if (tid == 0) {
            float s16[16]; float sn = 0.f;
#pragma unroll
            for (int o = 0; o < 16; o++) {
                float s = 0.f;
                for (int w2 = 0; w2 < 8; w2++) s += wred[w2*16 + o];
                s16[o] = s; sn += s*s;
            }
            float sc = sn/(1.f + sn) * rsqrtf(sn + 1e-12f);
#pragma unroll
            for (int o = 0; o < 16; o++) vv[o] = s16[o]*sc;
        }
        __syncthreads();
        if (it < 2) {
            for (int r = tid; r < R; r += 256) {
                const float* pr = P + r*16;
                float d = 0.f;
#pragma unroll
                for (int o = 0; o < 16; o++) d += pr[o]*vv[o];
                blog[r] += d;
            }
            __syncthreads();
        }
    }
    if (tid == 0) {
        float s = 0.f;
#pragma unroll
        for (int o = 0; o < 16; o++) s += vv[o]*vv[o];
        g_len[br*BATCH*NCLS + b*NCLS + n] = sqrtf(s + 1e-12f);
    }
}

// ---------------- final ----------------
__global__ void final_kernel(float* __restrict__ out) {
    int b = blockIdx.x*blockDim.x + threadIdx.x;
    if (b >= BATCH) return;
    float l[NCLS]; float mx = -1e30f;
#pragma unroll
    for (int n = 0; n < NCLS; n++) {
        l[n] = g_len[0*BATCH*NCLS + b*NCLS + n]
             + g_len[1*BATCH*NCLS + b*NCLS + n]
             + g_len[2*BATCH*NCLS + b*NCLS + n];
        mx = fmaxf(mx, l[n]);
    }
    float s = 0.f;
#pragma unroll
    for (int n = 0; n < NCLS; n++) { l[n] = expf(l[n] - mx); s += l[n]; }
    float inv = 1.f/s;
#pragma unroll
    for (int n = 0; n < NCLS; n++) out[b*NCLS + n] = l[n]*inv;
}

// ---------------- host driver ----------------
struct BranchCfg {
    int src;
    int H, k1, H1, kp, Hp, S, R, K;
    int iw, br;
    size_t yo, ko, wo, ao, po, uo, pro;
};

static void run_branch(const BranchCfg& c, void* const* d_in, const float* x,
                       cudaStream_t st)
{
    const float* cw = (const float*)d_in[c.iw + 0];
    const float* cb = (const float*)d_in[c.iw + 1];
    const float* pw = (const float*)d_in[c.iw + 2];
    const float* pb = (const float*)d_in[c.iw + 3];
    const float* dw = (const float*)d_in[c.iw + 4];

    int HW = c.H1*c.H1;
    if (c.k1 == 3)      convA_smem<3, 7, 5  ><<<BATCH, 256, 0, st>>>(x, c.src, cw, cb, c.yo);
    else if (c.k1 == 5) convA_smem<5, 14, 10><<<BATCH, 256, 0, st>>>(x, c.src, cw, cb, c.yo);
    else                convA_smem<9, 28, 20><<<BATCH, 256, 0, st>>>(x, c.src, cw, cb, c.yo);
    bn_stats_kernel<<<CC, 256, 0, st>>>(HW, c.yo, c.br);

    prep_w_kernel<<<(OCH*c.K + 255)/256, 256, 0, st>>>(pw, c.K, c.wo);
    prep_ktab_kernel<<<(c.K + 255)/256, 256, 0, st>>>(c.K, c.kp, c.H1, c.ko);

    int M = BATCH*c.S;
    im2col_kernel<<<M, 256, 0, st>>>(c.S, c.Hp, c.H1, c.K, c.yo, c.ko, c.ao, c.br);

    prim_mma_kernel<<<2*(M/128), 256, GSMEM, st>>>(pb, c.S, c.K, c.ao, c.wo, c.po);

    squash_u_kernel<<<(BATCH*c.R + 255)/256, 256, 0, st>>>(c.S, c.R, c.po, c.uo);

    dim3 pgrid(c.R, NCLS);
    priors_kernel<<<pgrid, 256, 0, st>>>(dw, c.R, c.uo, c.pro);

    int smemR = (c.R*17 + 128 + 16 + 8 + 2)*(int)sizeof(float);
    dim3 rgrid(BATCH, NCLS);
    routing_kernel<<<rgrid, 256, smemR, st>>>(c.R, c.br, c.pro);
}

extern "C" void kernel_launch(void* const* d_in, const int* in_sizes, int n_in,
                              void* d_out, int out_size)
{
    (void)in_sizes; (void)n_in; (void)out_size;
    const float* x = (const float*)d_in[0];
    float* out = (float*)d_out;

    static cudaStream_t st[3] = {0, 0, 0};
    static cudaEvent_t evRoot = 0, evPool = 0, evDone[3] = {0, 0, 0};
    if (!st[0]) {
        for (int i = 0; i < 3; i++)
            cudaStreamCreateWithFlags(&st[i], cudaStreamNonBlocking);
        cudaEventCreateWithFlags(&evRoot, cudaEventDisableTiming);
        cudaEventCreateWithFlags(&evPool, cudaEventDisableTiming);
        for (int i = 0; i < 3; i++)
            cudaEventCreateWithFlags(&evDone[i], cudaEventDisableTiming);
    }

    cudaFuncSetAttribute(routing_kernel, cudaFuncAttributeMaxDynamicSharedMemorySize, 96*1024);
    cudaFuncSetAttribute(prim_mma_kernel, cudaFuncAttributeMaxDynamicSharedMemorySize, GSMEM);

    //                src  H  k1 H1  kp Hp  S    R      K   iw br
    BranchCfg b1 = {   2,  7, 3,  5,  3, 2,  4,  128,  1152,  1, 0,
                       0,        0,    0,        0,        0,      0,      0 };
    BranchCfg b2 = {   1, 14, 5, 10,  5, 3,  9,  288,  3200,  6, 1,
                       819200,   1152, 294912,   1179648,  262144, 262144, 5242880 };
    BranchCfg b3 = {   0, 28, 9, 20,  9, 6, 36, 1152, 10368, 11, 2,
                       4096000,  4352, 1114112,  8552448,  851968, 851968, 17039360 };

    // fork
    cudaEventRecord(evRoot, 0);
    for (int i = 0; i < 3; i++) cudaStreamWaitEvent(st[i], evRoot, 0);

    // pools: pool2 on st[1] (b2 needs it), pool1 on st[0] after pool2
    pool2_kernel<<<(BATCH*14*14 + 255)/256, 256, 0, st[1]>>>(x);
    cudaEventRecord(evPool, st[1]);
    cudaStreamWaitEvent(st[0], evPool, 0);
    pool1_kernel<<<(BATCH*7*7 + 255)/256, 256, 0, st[0]>>>();

    run_branch(b3, d_in, x, st[2]);   // longest chain first
    run_branch(b2, d_in, x, st[1]);
    run_branch(b1, d_in, x, st[0]);

    // join
    for (int i = 0; i < 3; i++) {
        cudaEventRecord(evDone[i], st[i]);
        cudaStreamWaitEvent(0, evDone[i], 0);
    }
    final_kernel<<<1, 256>>>(out);
}

// round 6
// speedup vs baseline: 2.1996x; 1.1431x over previous
#include <cuda_runtime.h>
#include <cuda_bf16.h>
#include <math.h>
#include <stdint.h>

#define BATCH 256
#define NCLS  10
#define CC    128
#define OCH   256

// GEMM tiling: K-chunk 64
#define TSTRIDE 72                // bf16 elems per smem row (144B, 16B-aligned, conflict-free)
#define TILEB   (128*TSTRIDE*2)   // 18432 B per 128x64 bf16 tile
#define STAGEB  (4*TILEB)         // Ah,Al,Bh,Bl = 73728 B
#define GSMEM   (2*STAGEB)        // double buffered = 147456 B

// ---------------- static device scratch, per-branch offsets ----------------
__device__ float g_x2[BATCH*14*14];
__device__ float g_x1[BATCH*7*7];
__device__ float g_y [17203200];            // b1:819200 b2:3276800 b3:13107200
__device__ float g_mean[3*CC];
__device__ float g_rstd[3*CC];
__device__ float g_bnp[3*CC*8*2];           // partial sums [br][c][slice][{s,s2}]
__device__ int   g_ktab[14720];             // b1:1152 b2:3200 b3:10368
__device__ __nv_bfloat16 g_wh[3768320];     // OCH*K per branch
__device__ __nv_bfloat16 g_wl[3768320];
__device__ __nv_bfloat16 g_Ah[104103936];   // M*K per branch
__device__ __nv_bfloat16 g_Al[104103936];
__device__ float g_p [3211264];             // [m][oc] per branch
__device__ float g_u [3211264];
__device__ float g_priors[64225280];
__device__ float g_len[3*BATCH*NCLS];

// ---------------- PTX helpers ----------------
__device__ __forceinline__ uint32_t smem_u32(const void* p) {
    uint32_t a;
    asm("{ .reg .u64 t; cvta.to.shared.u64 t, %1; cvt.u32.u64 %0, t; }" : "=r"(a) : "l"(p));
    return a;
}
#define CP_ASYNC16(dst, src) \
    asm volatile("cp.async.ca.shared.global [%0], [%1], 16;" :: "r"(dst), "l"(src) : "memory")
#define CP_COMMIT() asm volatile("cp.async.commit_group;" ::: "memory")
#define CP_WAIT0()  asm volatile("cp.async.wait_group 0;" ::: "memory")
#define CP_WAIT1()  asm volatile("cp.async.wait_group 1;" ::: "memory")

__device__ __forceinline__ void ldmx4(uint32_t addr, uint32_t& r0, uint32_t& r1,
                                      uint32_t& r2, uint32_t& r3) {
    asm volatile("ldmatrix.sync.aligned.m8n8.x4.shared.b16 {%0,%1,%2,%3}, [%4];"
                 : "=r"(r0), "=r"(r1), "=r"(r2), "=r"(r3) : "r"(addr));
}
__device__ __forceinline__ void mma16816(float* c, const uint32_t* a, uint32_t b0, uint32_t b1) {
    asm volatile(
        "mma.sync.aligned.m16n8k16.row.col.f32.bf16.bf16.f32 "
        "{%0,%1,%2,%3}, {%4,%5,%6,%7}, {%8,%9}, {%0,%1,%2,%3};"
        : "+f"(c[0]), "+f"(c[1]), "+f"(c[2]), "+f"(c[3])
        : "r"(a[0]), "r"(a[1]), "r"(a[2]), "r"(a[3]), "r"(b0), "r"(b1));
}

// ---------------- pooling ----------------
__global__ void pool2_kernel(const float* __restrict__ img) {
    int idx = blockIdx.x*blockDim.x + threadIdx.x;
    if (idx >= BATCH*14*14) return;
    int j = idx % 14, i = (idx/14) % 14, b = idx/196;
    const float* p = img + b*784;
    g_x2[idx] = 0.25f*(p[(2*i)*28+2*j] + p[(2*i)*28+2*j+1]
                     + p[(2*i+1)*28+2*j] + p[(2*i+1)*28+2*j+1]);
}
__global__ void pool1_kernel() {
    int idx = blockIdx.x*blockDim.x + threadIdx.x;
    if (idx >= BATCH*7*7) return;
    int j = idx % 7, i = (idx/7) % 7, b = idx/49;
    const float* p = g_x2 + b*196;
    g_x1[idx] = 0.25f*(p[(2*i)*14+2*j] + p[(2*i)*14+2*j+1]
                     + p[(2*i+1)*14+2*j] + p[(2*i+1)*14+2*j+1]);
}

// ---------------- conv stage A: smem-tiled, compile-time k ----------------
template<int K1, int H, int H1>
__global__ __launch_bounds__(256) void convA_smem(const float* __restrict__ xin_ext, int src,
                                                  const float* __restrict__ w,
                                                  const float* __restrict__ bias,
                                                  size_t yo)
{
    __shared__ float s_in[H*H];
    __shared__ float s_w[CC*K1*K1];
    int b = blockIdx.x;
    int tid = threadIdx.x;
    const float* xin = (src == 0) ? xin_ext : (src == 1 ? g_x2 : g_x1);
    const float* ip = xin + b*H*H;
    for (int i = tid; i < H*H; i += 256) s_in[i] = ip[i];
    for (int i = tid; i < CC*K1*K1; i += 256) s_w[i] = w[i];
    __syncthreads();

    for (int pair = tid; pair < CC*H1; pair += 256) {
        int c = pair & (CC-1), oy = pair >> 7;
        float bv = __ldg(&bias[c]);
        float acc[H1];
#pragma unroll
        for (int ox = 0; ox < H1; ox++) acc[ox] = bv;
        const float* wc = s_w + c*K1*K1;
#pragma unroll
        for (int ky = 0; ky < K1; ky++) {
            float row[H1 + K1 - 1];
            const float* rp = s_in + (oy + ky)*H;
#pragma unroll
            for (int x = 0; x < H1 + K1 - 1; x++) row[x] = rp[x];
#pragma unroll
            for (int kx = 0; kx < K1; kx++) {
                float wv = wc[ky*K1 + kx];
#pragma unroll
                for (int ox = 0; ox < H1; ox++)
                    acc[ox] = fmaf(wv, row[ox + kx], acc[ox]);
            }
        }
        float* op = g_y + yo + ((size_t)(b*CC + c)*H1 + oy)*H1;
#pragma unroll
        for (int ox = 0; ox < H1; ox++) op[ox] = fmaxf(acc[ox], 0.f);
    }
}

// ---------------- batchnorm: two-phase reduction ----------------
__global__ void bn_partial_kernel(int HW, size_t yo, int br) {
    int c = blockIdx.x, sl = blockIdx.y;
    int tid = threadIdx.x;
    const float* yb = g_y + yo;
    float s = 0.f, s2 = 0.f;
    int total = 32*HW;                 // 32 batch images per slice
    for (int i = tid; i < total; i += 256) {
        int b = sl*32 + i/HW;
        int hw = i - (i/HW)*HW;
        float v = yb[(size_t)(b*CC + c)*HW + hw];
        s += v; s2 += v*v;
    }
#pragma unroll
    for (int off = 16; off; off >>= 1) {
        s  += __shfl_xor_sync(0xffffffffu, s,  off);
        s2 += __shfl_xor_sync(0xffffffffu, s2, off);
    }
    __shared__ float rs[8], rq[8];
    if ((tid & 31) == 0) { rs[tid>>5] = s; rq[tid>>5] = s2; }
    __syncthreads();
    if (tid == 0) {
        float a = 0.f, b2 = 0.f;
#pragma unroll
        for (int w = 0; w < 8; w++) { a += rs[w]; b2 += rq[w]; }
        g_bnp[((br*CC + c)*8 + sl)*2 + 0] = a;
        g_bnp[((br*CC + c)*8 + sl)*2 + 1] = b2;
    }
}
__global__ void bn_final_kernel(int HW, int br) {
    int c = threadIdx.x;
    float s = 0.f, s2 = 0.f;
#pragma unroll
    for (int sl = 0; sl < 8; sl++) {
        s  += g_bnp[((br*CC + c)*8 + sl)*2 + 0];
        s2 += g_bnp[((br*CC + c)*8 + sl)*2 + 1];
    }
    float N = (float)(BATCH*HW);
    float m = s / N;
    float var = s2 / N - m*m;
    g_mean[br*CC + c] = m;
    g_rstd[br*CC + c] = rsqrtf(var + 1e-5f);
}

// ---------------- prep ----------------
__global__ void prep_w_kernel(const float* __restrict__ pw, int K, size_t wo) {
    int idx = blockIdx.x*blockDim.x + threadIdx.x;
    if (idx >= OCH*K) return;
    float v = pw[idx];
    __nv_bfloat16 h = __float2bfloat16(v);
    g_wh[wo + idx] = h;
    g_wl[wo + idx] = __float2bfloat16(v - __bfloat162float(h));
}
__global__ void prep_ktab_kernel(int K, int kp, int H1, size_t ko) {
    int kidx = blockIdx.x*blockDim.x + threadIdx.x;
    if (kidx >= K) return;
    int kk2 = kp*kp;
    int ic = kidx / kk2;
    int rem = kidx - ic*kk2;
    int off = ic*H1*H1 + (rem/kp)*H1 + (rem % kp);
    g_ktab[ko + kidx] = (ic << 20) | off;
}
__global__ void im2col_kernel(int S, int Hp, int H1, int K,
                              size_t yo, size_t ko, size_t ao, int br) {
    int m = blockIdx.x;
    int b = m / S, s = m - b*S;
    int oy = s / Hp, ox = s - oy*Hp;
    const float* src = g_y + yo + (size_t)(b*CC)*H1*H1 + (oy*2)*H1 + ox*2;
    const int* kt = g_ktab + ko;
    const float* mean = g_mean + br*CC;
    const float* rstd = g_rstd + br*CC;
    size_t base = ao + (size_t)m*K;
    __nv_bfloat162* dh = reinterpret_cast<__nv_bfloat162*>(g_Ah + base);
    __nv_bfloat162* dl = reinterpret_cast<__nv_bfloat162*>(g_Al + base);
    for (int k2 = threadIdx.x; k2*2 < K; k2 += blockDim.x) {
        int t0 = kt[k2*2], t1 = kt[k2*2 + 1];
        int c0 = t0 >> 20, c1 = t1 >> 20;
        float v0 = (src[t0 & 0xFFFFF] - mean[c0]) * rstd[c0];
        float v1 = (src[t1 & 0xFFFFF] - mean[c1]) * rstd[c1];
        __nv_bfloat16 h0 = __float2bfloat16(v0);
        __nv_bfloat16 h1 = __float2bfloat16(v1);
        dh[k2] = __halves2bfloat162(h0, h1);
        dl[k2] = __halves2bfloat162(__float2bfloat16(v0 - __bfloat162float(h0)),
                                    __float2bfloat16(v1 - __bfloat162float(h1)));
    }
}

// ---------------- prim conv GEMM: mma.sync bf16 split, 128x128 tile, KC=64 ----------------
__device__ __forceinline__ void load_stage(uint32_t sb, int buf,
                                           int m0, int n0, int kc, int K,
                                           size_t ao, size_t wo, int tid)
{
    uint32_t dst0 = sb + buf*STAGEB;
#pragma unroll
    for (int i = 0; i < 16; i++) {
        int q = tid + i*256;
        int mat = q >> 10;             // 0:Ah 1:Al 2:Bh 3:Bl
        int w = q & 1023;
        int row = w >> 3;
        int ch  = w & 7;
        const __nv_bfloat16* gsrc;
        if      (mat == 0) gsrc = g_Ah + ao + (size_t)(m0 + row)*K + kc + ch*8;
        else if (mat == 1) gsrc = g_Al + ao + (size_t)(m0 + row)*K + kc + ch*8;
        else if (mat == 2) gsrc = g_wh + wo + (size_t)(n0 + row)*K + kc + ch*8;
        else               gsrc = g_wl + wo + (size_t)(n0 + row)*K + kc + ch*8;
        uint32_t dst = dst0 + mat*TILEB + row*(TSTRIDE*2) + ch*16;
        CP_ASYNC16(dst, gsrc);
    }
}

__global__ __launch_bounds__(256) void prim_mma_kernel(const float* __restrict__ pb,
                                                       int S, int K,
                                                       size_t ao, size_t wo, size_t po)
{
    extern __shared__ char smem[];
    uint32_t sb = smem_u32(smem);
    int tid = threadIdx.x, wid = tid >> 5, lane = tid & 31;
    int n0 = (blockIdx.x & 1) << 7;
    int m0 = (int)(blockIdx.x >> 1) << 7;

    int wm = (wid & 3) << 5;   // warp m-origin (32-row slab)
    int wn = (wid >> 2) << 6;  // warp n-origin (64-col slab)

    float acc[2][8][4];
#pragma unroll
    for (int mt = 0; mt < 2; mt++)
#pragma unroll
        for (int nb = 0; nb < 8; nb++)
#pragma unroll
            for (int j = 0; j < 4; j++) acc[mt][nb][j] = 0.f;

    int nch = K >> 6;
    load_stage(sb, 0, m0, n0, 0, K, ao, wo, tid);
    CP_COMMIT();

    uint32_t aLaneOff = (uint32_t)((lane & 15)*(TSTRIDE*2) + (lane >> 4)*16);
    uint32_t bLaneOff = (uint32_t)((((lane >> 3) & 3)*8 + (lane & 7))*(TSTRIDE*2));

    for (int c = 0; c < nch; c++) {
        int buf = c & 1;
        if (c + 1 < nch) {
            load_stage(sb, buf ^ 1, m0, n0, (c + 1) << 6, K, ao, wo, tid);
            CP_COMMIT();
            CP_WAIT1();
        } else {
            CP_WAIT0();
        }
        __syncthreads();

        uint32_t st = sb + buf*STAGEB;
#pragma unroll
        for (int kk = 0; kk < 4; kk++) {
            uint32_t ah[2][4], al[2][4];
#pragma unroll
            for (int mt = 0; mt < 2; mt++)
                ldmx4(st + (wm + mt*16)*(TSTRIDE*2) + kk*32 + aLaneOff,
                      ah[mt][0], ah[mt][1], ah[mt][2], ah[mt][3]);
            uint32_t bh[8][2], bl[8][2];
#pragma unroll
            for (int g = 0; g < 2; g++)
#pragma unroll
                for (int kh = 0; kh < 2; kh++) {
                    uint32_t r0, r1, r2, r3;
                    ldmx4(st + 2*TILEB + (wn + g*32)*(TSTRIDE*2) + kk*32 + kh*16 + bLaneOff,
                          r0, r1, r2, r3);
                    bh[g*4+0][kh] = r0; bh[g*4+1][kh] = r1;
                    bh[g*4+2][kh] = r2; bh[g*4+3][kh] = r3;
                    ldmx4(st + 3*TILEB + (wn + g*32)*(TSTRIDE*2) + kk*32 + kh*16 + bLaneOff,
                          r0, r1, r2, r3);
                    bl[g*4+0][kh] = r0; bl[g*4+1][kh] = r1;
                    bl[g*4+2][kh] = r2; bl[g*4+3][kh] = r3;
                }
#pragma unroll
            for (int mt = 0; mt < 2; mt++)
#pragma unroll
                for (int nb = 0; nb < 8; nb++)
                    mma16816(acc[mt][nb], ah[mt], bh[nb][0], bh[nb][1]);
#pragma unroll
            for (int mt = 0; mt < 2; mt++)
#pragma unroll
                for (int nb = 0; nb < 8; nb++)
                    mma16816(acc[mt][nb], ah[mt], bl[nb][0], bl[nb][1]);
#pragma unroll
            for (int mt = 0; mt < 2; mt++)
                ldmx4(st + TILEB + (wm + mt*16)*(TSTRIDE*2) + kk*32 + aLaneOff,
                      al[mt][0], al[mt][1], al[mt][2], al[mt][3]);
#pragma unroll
            for (int mt = 0; mt < 2; mt++)
#pragma unroll
                for (int nb = 0; nb < 8; nb++)
                    mma16816(acc[mt][nb], al[mt], bh[nb][0], bh[nb][1]);
        }
        __syncthreads();
    }

    // epilogue: g_p layout [m][oc], coalesced 8B pairs
    int gr = lane >> 2, tc = lane & 3;
    float* gp = g_p + po;
#pragma unroll
    for (int mt = 0; mt < 2; mt++) {
        int mA = m0 + wm + mt*16 + gr;
        int mB = mA + 8;
#pragma unroll
        for (int nb = 0; nb < 8; nb++) {
            int oc = n0 + wn + nb*8 + tc*2;
            float bias0 = pb[oc], bias1 = pb[oc+1];
            float2 vA = make_float2(acc[mt][nb][0] + bias0, acc[mt][nb][1] + bias1);
            float2 vB = make_float2(acc[mt][nb][2] + bias0, acc[mt][nb][3] + bias1);
            *reinterpret_cast<float2*>(gp + (size_t)mA*OCH + oc) = vA;
            *reinterpret_cast<float2*>(gp + (size_t)mB*OCH + oc) = vB;
        }
    }
}

// ---------------- squash primary capsules ----------------
__global__ void squash_u_kernel(int S, int R, size_t po, size_t uo) {
    int idx = blockIdx.x*blockDim.x + threadIdx.x;
    if (idx >= BATCH*R) return;
    int r = idx % R, b = idx / R;
    int c32 = r / S, s = r - c32*S;
    const float* pp = g_p + po + (size_t)(b*S + s)*OCH + c32;
    float t[8]; float sn = 0.f;
#pragma unroll
    for (int i = 0; i < 8; i++) {
        t[i] = pp[i*32];
        sn += t[i]*t[i];
    }
    float scale = sn/(1.f + sn) * rsqrtf(sn + 1e-12f);
    float* up = g_u + uo + (size_t)idx*8;
#pragma unroll
    for (int i = 0; i < 8; i++)
        up[i] = t[i]*scale;
}

// ---------------- priors ----------------
__global__ void priors_kernel(const float* __restrict__ dw, int R, size_t uo, size_t pro) {
    int r = blockIdx.x, n = blockIdx.y;
    __shared__ float w[128];
    if (threadIdx.x < 128)
        w[threadIdx.x] = dw[((size_t)n*R + r)*128 + threadIdx.x];
    __syncthreads();
    int b = threadIdx.x;
    float u[8];
    const float* up = g_u + uo + ((size_t)b*R + r)*8;
#pragma unroll
    for (int i = 0; i < 8; i++) u[i] = up[i];
    float* out = g_priors + pro + (((size_t)n*BATCH + b)*R + r)*16;
#pragma unroll
    for (int o = 0; o < 16; o++) {
        float s = 0.f;
#pragma unroll
        for (int i = 0; i < 8; i++) s += u[i]*w[i*16 + o];
        out[o] = s;
    }
}

// ---------------- dynamic routing ----------------
__global__ void routing_kernel(int R, int br, size_t pro) {
    int b = blockIdx.x, n = blockIdx.y;
    extern __shared__ float sm[];
    float* P    = sm;
    float* blog = P + R*16;
    float* wred = blog + R;
    float* vv   = wred + 128;
    float* sred = vv + 16;
    float* scal = sred + 8;

    int tid = threadIdx.x;
    const float* gp = g_priors + pro + (((size_t)n*BATCH + b)*R)*16;
    for (int i = tid; i < R*16; i += 256) P[i] = gp[i];
    for (int r = tid; r < R;    r += 256) blog[r] = 0.f;
    __syncthreads();

    for (int it = 0; it < 3; it++) {
        float mx = -1e30f;
        for (int r = tid; r < R; r += 256) mx = fmaxf(mx, blog[r]);
#pragma unroll
        for (int off = 16; off; off >>= 1)
            mx = fmaxf(mx, __shfl_xor_sync(0xffffffffu, mx, off));
        if ((tid & 31) == 0) sred[tid >> 5] = mx;
        __syncthreads();
        if (tid == 0) {
            float m = sred[0];
            for (int w2 = 1; w2 < 8; w2++) m = fmaxf(m, sred[w2]);
            scal[0] = m;
        }
        __syncthreads();
        float gmax = scal[0];
        float se = 0.f;
        for (int r = tid; r < R; r += 256) se += expf(blog[r] - gmax);
#pragma unroll
        for (int off = 16; off; off >>= 1)
            se += __shfl_xor_sync(0xffffffffu, se, off);
        if ((tid & 31) == 0) sred[tid >> 5] = se;
        __syncthreads();
        if (tid == 0) {
            float s = 0.f;
            for (int w2 = 0; w2 < 8; w2++) s += sred[w2];
            scal[1] = 1.f/s;
        }
        __syncthreads();
        float isum = scal[1];
        float acc[16];
#pragma unroll
        for (int o = 0; o < 16; o++) acc[o] = 0.f;
        for (int r = tid; r < R; r += 256) {
            float c = expf(blog[r] - gmax)*isum;
            const float* pr = P + r*16;
#pragma unroll
            for (int o = 0; o < 16; o++) acc[o] += c*pr[o];
        }
#pragma unroll
        for (int o = 0; o < 16; o++) {
            float v = acc[o];
#pragma unroll
            for (int off = 16; off; off >>= 1)
                v += __shfl_xor_sync(0xffffffffu, v, off);
            acc[o] = v;
        }
        if ((tid & 31) == 0)
#pragma unroll
            for (int o = 0; o < 16; o++) wred[(tid >> 5)*16 + o] = acc[o];
        __syncthreads();
        if (tid == 0) {
            float s16[16]; float sn = 0.f;
#pragma unroll
            for (int o = 0; o < 16; o++) {
                float s = 0.f;
                for (int w2 = 0; w2 < 8; w2++) s += wred[w2*16 + o];
                s16[o] = s; sn += s*s;
            }
            float sc = sn/(1.f + sn) * rsqrtf(sn + 1e-12f);
#pragma unroll
            for (int o = 0; o < 16; o++) vv[o] = s16[o]*sc;
        }
        __syncthreads();
        if (it < 2) {
            for (int r = tid; r < R; r += 256) {
                const float* pr = P + r*16;
                float d = 0.f;
#pragma unroll
                for (int o = 0; o < 16; o++) d += pr[o]*vv[o];
                blog[r] += d;
            }
            __syncthreads();
        }
    }
    if (tid == 0) {
        float s = 0.f;
#pragma unroll
        for (int o = 0; o < 16; o++) s += vv[o]*vv[o];
        g_len[br*BATCH*NCLS + b*NCLS + n] = sqrtf(s + 1e-12f);
    }
}

// ---------------- final ----------------
__global__ void final_kernel(float* __restrict__ out) {
    int b = blockIdx.x*blockDim.x + threadIdx.x;
    if (b >= BATCH) return;
    float l[NCLS]; float mx = -1e30f;
#pragma unroll
    for (int n = 0; n < NCLS; n++) {
        l[n] = g_len[0*BATCH*NCLS + b*NCLS + n]
             + g_len[1*BATCH*NCLS + b*NCLS + n]
             + g_len[2*BATCH*NCLS + b*NCLS + n];
        mx = fmaxf(mx, l[n]);
    }
    float s = 0.f;
#pragma unroll
    for (int n = 0; n < NCLS; n++) { l[n] = expf(l[n] - mx); s += l[n]; }
    float inv = 1.f/s;
#pragma unroll
    for (int n = 0; n < NCLS; n++) out[b*NCLS + n] = l[n]*inv;
}

// ---------------- host driver ----------------
struct BranchCfg {
    int src;
    int H, k1, H1, kp, Hp, S, R, K;
    int iw, br;
    size_t yo, ko, wo, ao, po, uo, pro;
};

static void run_branch(const BranchCfg& c, void* const* d_in, const float* x,
                       cudaStream_t st)
{
    const float* cw = (const float*)d_in[c.iw + 0];
    const float* cb = (const float*)d_in[c.iw + 1];
    const float* pw = (const float*)d_in[c.iw + 2];
    const float* pb = (const float*)d_in[c.iw + 3];
    const float* dw = (const float*)d_in[c.iw + 4];

    int HW = c.H1*c.H1;
    if (c.k1 == 3)      convA_smem<3, 7, 5  ><<<BATCH, 256, 0, st>>>(x, c.src, cw, cb, c.yo);
    else if (c.k1 == 5) convA_smem<5, 14, 10><<<BATCH, 256, 0, st>>>(x, c.src, cw, cb, c.yo);
    else                convA_smem<9, 28, 20><<<BATCH, 256, 0, st>>>(x, c.src, cw, cb, c.yo);
    bn_partial_kernel<<<dim3(CC, 8), 256, 0, st>>>(HW, c.yo, c.br);
    bn_final_kernel<<<1, CC, 0, st>>>(HW, c.br);

    prep_w_kernel<<<(OCH*c.K + 255)/256, 256, 0, st>>>(pw, c.K, c.wo);
    prep_ktab_kernel<<<(c.K + 255)/256, 256, 0, st>>>(c.K, c.kp, c.H1, c.ko);

    int M = BATCH*c.S;
    im2col_kernel<<<M, 256, 0, st>>>(c.S, c.Hp, c.H1, c.K, c.yo, c.ko, c.ao, c.br);

    prim_mma_kernel<<<2*(M/128), 256, GSMEM, st>>>(pb, c.S, c.K, c.ao, c.wo, c.po);

    squash_u_kernel<<<(BATCH*c.R + 255)/256, 256, 0, st>>>(c.S, c.R, c.po, c.uo);

    dim3 pgrid(c.R, NCLS);
    priors_kernel<<<pgrid, 256, 0, st>>>(dw, c.R, c.uo, c.pro);

    int smemR = (c.R*17 + 128 + 16 + 8 + 2)*(int)sizeof(float);
    dim3 rgrid(BATCH, NCLS);
    routing_kernel<<<rgrid, 256, smemR, st>>>(c.R, c.br, c.pro);
}

extern "C" void kernel_launch(void* const* d_in, const int* in_sizes, int n_in,
                              void* d_out, int out_size)
{
    (void)in_sizes; (void)n_in; (void)out_size;
    const float* x = (const float*)d_in[0];
    float* out = (float*)d_out;

    static cudaStream_t st[3] = {0, 0, 0};
    static cudaEvent_t evRoot = 0, evPool = 0, evDone[3] = {0, 0, 0};
    if (!st[0]) {
        for (int i = 0; i < 3; i++)
            cudaStreamCreateWithFlags(&st[i], cudaStreamNonBlocking);
        cudaEventCreateWithFlags(&evRoot, cudaEventDisableTiming);
        cudaEventCreateWithFlags(&evPool, cudaEventDisableTiming);
        for (int i = 0; i < 3; i++)
            cudaEventCreateWithFlags(&evDone[i], cudaEventDisableTiming);
    }

    cudaFuncSetAttribute(routing_kernel, cudaFuncAttributeMaxDynamicSharedMemorySize, 96*1024);
    cudaFuncSetAttribute(prim_mma_kernel, cudaFuncAttributeMaxDynamicSharedMemorySize, GSMEM);

    //                src  H  k1 H1  kp Hp  S    R      K   iw br
    BranchCfg b1 = {   2,  7, 3,  5,  3, 2,  4,  128,  1152,  1, 0,
                       0,        0,    0,        0,        0,      0,      0 };
    BranchCfg b2 = {   1, 14, 5, 10,  5, 3,  9,  288,  3200,  6, 1,
                       819200,   1152, 294912,   1179648,  262144, 262144, 5242880 };
    BranchCfg b3 = {   0, 28, 9, 20,  9, 6, 36, 1152, 10368, 11, 2,
                       4096000,  4352, 1114112,  8552448,  851968, 851968, 17039360 };

    // fork
    cudaEventRecord(evRoot, 0);
    for (int i = 0; i < 3; i++) cudaStreamWaitEvent(st[i], evRoot, 0);

    // pools: pool2 on st[1] (b2 needs it), pool1 on st[0] after pool2
    pool2_kernel<<<(BATCH*14*14 + 255)/256, 256, 0, st[1]>>>(x);
    cudaEventRecord(evPool, st[1]);
    cudaStreamWaitEvent(st[0], evPool, 0);
    pool1_kernel<<<(BATCH*7*7 + 255)/256, 256, 0, st[0]>>>();

    run_branch(b3, d_in, x, st[2]);   // longest chain first
    run_branch(b2, d_in, x, st[1]);
    run_branch(b1, d_in, x, st[0]);

    // join
    for (int i = 0; i < 3; i++) {
        cudaEventRecord(evDone[i], st[i]);
        cudaStreamWaitEvent(0, evDone[i], 0);
    }
    final_kernel<<<1, 256>>>(out);
}

// round 7
// speedup vs baseline: 2.5946x; 1.1796x over previous
#include <cuda_runtime.h>
#include <cuda_bf16.h>
#include <math.h>
#include <stdint.h>

#define BATCH 256
#define NCLS  10
#define CC    128
#define OCH   256

// GEMM tiling: KC=32
#define TSTRIDE 40                // bf16 elems per smem row (80B)
#define TILEB   (128*TSTRIDE*2)   // 10240 B per 128x32 bf16 tile
#define STAGEB  (4*TILEB)         // Ah,Al,Bh,Bl = 40960 B
#define GSMEM0  (2*STAGEB)        // double buffered = 81920 B (+ ktab)

// ---------------- static device scratch, per-branch offsets ----------------
__device__ float g_x2[BATCH*14*14];
__device__ float g_x1[BATCH*7*7];
__device__ float g_y [17203200];            // b1:819200 b2:3276800 b3:13107200
__device__ float g_mean[3*CC];
__device__ float g_rstd[3*CC];
__device__ float g_bnp[3*CC*8*2];
__device__ float g_badj[3*OCH];
__device__ int   g_ktab[14720];             // (channel<<20)|offset; b1:1152 b2:3200 b3:10368
__device__ __nv_bfloat16 g_wh[3768320];     // BN-scaled split weights per branch
__device__ __nv_bfloat16 g_wl[3768320];
__device__ float g_p [3211264];             // [m][oc] per branch
__device__ float g_u [3211264];
__device__ float g_len[3*BATCH*NCLS];

// ---------------- PTX helpers ----------------
__device__ __forceinline__ uint32_t smem_u32(const void* p) {
    uint32_t a;
    asm("{ .reg .u64 t; cvta.to.shared.u64 t, %1; cvt.u32.u64 %0, t; }" : "=r"(a) : "l"(p));
    return a;
}
#define CP_ASYNC16(dst, src) \
    asm volatile("cp.async.ca.shared.global [%0], [%1], 16;" :: "r"(dst), "l"(src) : "memory")
#define CP_COMMIT() asm volatile("cp.async.commit_group;" ::: "memory")
#define CP_WAIT0()  asm volatile("cp.async.wait_group 0;" ::: "memory")

__device__ __forceinline__ void ldmx4(uint32_t addr, uint32_t& r0, uint32_t& r1,
                                      uint32_t& r2, uint32_t& r3) {
    asm volatile("ldmatrix.sync.aligned.m8n8.x4.shared.b16 {%0,%1,%2,%3}, [%4];"
                 : "=r"(r0), "=r"(r1), "=r"(r2), "=r"(r3) : "r"(addr));
}
__device__ __forceinline__ void mma16816(float* c, const uint32_t* a, uint32_t b0, uint32_t b1) {
    asm volatile(
        "mma.sync.aligned.m16n8k16.row.col.f32.bf16.bf16.f32 "
        "{%0,%1,%2,%3}, {%4,%5,%6,%7}, {%8,%9}, {%0,%1,%2,%3};"
        : "+f"(c[0]), "+f"(c[1]), "+f"(c[2]), "+f"(c[3])
        : "r"(a[0]), "r"(a[1]), "r"(a[2]), "r"(a[3]), "r"(b0), "r"(b1));
}

// ---------------- pooling ----------------
__global__ void pool2_kernel(const float* __restrict__ img) {
    int idx = blockIdx.x*blockDim.x + threadIdx.x;
    if (idx >= BATCH*14*14) return;
    int j = idx % 14, i = (idx/14) % 14, b = idx/196;
    const float* p = img + b*784;
    g_x2[idx] = 0.25f*(p[(2*i)*28+2*j] + p[(2*i)*28+2*j+1]
                     + p[(2*i+1)*28+2*j] + p[(2*i+1)*28+2*j+1]);
}
__global__ void pool1_kernel() {
    int idx = blockIdx.x*blockDim.x + threadIdx.x;
    if (idx >= BATCH*7*7) return;
    int j = idx % 7, i = (idx/7) % 7, b = idx/49;
    const float* p = g_x2 + b*196;
    g_x1[idx] = 0.25f*(p[(2*i)*14+2*j] + p[(2*i)*14+2*j+1]
                     + p[(2*i+1)*14+2*j] + p[(2*i+1)*14+2*j+1]);
}

// ---------------- conv stage A ----------------
template<int K1, int H, int H1>
__global__ __launch_bounds__(256) void convA_smem(const float* __restrict__ xin_ext, int src,
                                                  const float* __restrict__ w,
                                                  const float* __restrict__ bias,
                                                  size_t yo)
{
    __shared__ float s_in[H*H];
    __shared__ float s_w[CC*K1*K1];
    int b = blockIdx.x;
    int tid = threadIdx.x;
    const float* xin = (src == 0) ? xin_ext : (src == 1 ? g_x2 : g_x1);
    const float* ip = xin + b*H*H;
    for (int i = tid; i < H*H; i += 256) s_in[i] = ip[i];
    for (int i = tid; i < CC*K1*K1; i += 256) s_w[i] = w[i];
    __syncthreads();

    for (int pair = tid; pair < CC*H1; pair += 256) {
        int c = pair & (CC-1), oy = pair >> 7;
        float bv = __ldg(&bias[c]);
        float acc[H1];
#pragma unroll
        for (int ox = 0; ox < H1; ox++) acc[ox] = bv;
        const float* wc = s_w + c*K1*K1;
#pragma unroll
        for (int ky = 0; ky < K1; ky++) {
            float row[H1 + K1 - 1];
            const float* rp = s_in + (oy + ky)*H;
#pragma unroll
            for (int x = 0; x < H1 + K1 - 1; x++) row[x] = rp[x];
#pragma unroll
            for (int kx = 0; kx < K1; kx++) {
                float wv = wc[ky*K1 + kx];
#pragma unroll
                for (int ox = 0; ox < H1; ox++)
                    acc[ox] = fmaf(wv, row[ox + kx], acc[ox]);
            }
        }
        float* op = g_y + yo + ((size_t)(b*CC + c)*H1 + oy)*H1;
#pragma unroll
        for (int ox = 0; ox < H1; ox++) op[ox] = fmaxf(acc[ox], 0.f);
    }
}

// ---------------- batchnorm stats: two-phase ----------------
__global__ void bn_partial_kernel(int HW, size_t yo, int br) {
    int c = blockIdx.x, sl = blockIdx.y;
    int tid = threadIdx.x;
    const float* yb = g_y + yo;
    float s = 0.f, s2 = 0.f;
    int total = 32*HW;
    for (int i = tid; i < total; i += 256) {
        int b = sl*32 + i/HW;
        int hw = i - (i/HW)*HW;
        float v = yb[(size_t)(b*CC + c)*HW + hw];
        s += v; s2 += v*v;
    }
#pragma unroll
    for (int off = 16; off; off >>= 1) {
        s  += __shfl_xor_sync(0xffffffffu, s,  off);
        s2 += __shfl_xor_sync(0xffffffffu, s2, off);
    }
    __shared__ float rs[8], rq[8];
    if ((tid & 31) == 0) { rs[tid>>5] = s; rq[tid>>5] = s2; }
    __syncthreads();
    if (tid == 0) {
        float a = 0.f, b2 = 0.f;
#pragma unroll
        for (int w = 0; w < 8; w++) { a += rs[w]; b2 += rq[w]; }
        g_bnp[((br*CC + c)*8 + sl)*2 + 0] = a;
        g_bnp[((br*CC + c)*8 + sl)*2 + 1] = b2;
    }
}
__global__ void bn_final_kernel(int HW, int br) {
    int c = threadIdx.x;
    float s = 0.f, s2 = 0.f;
#pragma unroll
    for (int sl = 0; sl < 8; sl++) {
        s  += g_bnp[((br*CC + c)*8 + sl)*2 + 0];
        s2 += g_bnp[((br*CC + c)*8 + sl)*2 + 1];
    }
    float N = (float)(BATCH*HW);
    float m = s / N;
    float var = s2 / N - m*m;
    g_mean[br*CC + c] = m;
    g_rstd[br*CC + c] = rsqrtf(var + 1e-5f);
}

// ---------------- prep: ktab, BN-folded split weights, bias adjust ----------------
__global__ void prep_ktab_kernel(int K, int kp, int H1, size_t ko) {
    int kidx = blockIdx.x*blockDim.x + threadIdx.x;
    if (kidx >= K) return;
    int kk2 = kp*kp;
    int ic = kidx / kk2;
    int rem = kidx - ic*kk2;
    int off = ic*H1*H1 + (rem/kp)*H1 + (rem % kp);
    g_ktab[ko + kidx] = (ic << 20) | off;
}
// w' = pw * rstd[c]; split to (hi,lo) bf16
__global__ void prep_w_kernel(const float* __restrict__ pw, int K, size_t wo,
                              size_t ko, int br) {
    int idx = blockIdx.x*blockDim.x + threadIdx.x;
    if (idx >= OCH*K) return;
    int k = idx - (idx/K)*K;
    int c = g_ktab[ko + k] >> 20;
    float v = pw[idx] * g_rstd[br*CC + c];
    __nv_bfloat16 h = __float2bfloat16(v);
    g_wh[wo + idx] = h;
    g_wl[wo + idx] = __float2bfloat16(v - __bfloat162float(h));
}
// badj[oc] = pb[oc] - sum_k pw[oc][k]*mean[c]*rstd[c]
__global__ void prep_badj_kernel(const float* __restrict__ pw,
                                 const float* __restrict__ pb,
                                 int K, size_t ko, int br) {
    int oc = blockIdx.x;
    int tid = threadIdx.x;
    float s = 0.f;
    for (int k = tid; k < K; k += 256) {
        int c = g_ktab[ko + k] >> 20;
        s += pw[(size_t)oc*K + k] * g_mean[br*CC + c] * g_rstd[br*CC + c];
    }
#pragma unroll
    for (int off = 16; off; off >>= 1) s += __shfl_xor_sync(0xffffffffu, s, off);
    __shared__ float rs[8];
    if ((tid & 31) == 0) rs[tid>>5] = s;
    __syncthreads();
    if (tid == 0) {
        float a = 0.f;
#pragma unroll
        for (int w = 0; w < 8; w++) a += rs[w];
        g_badj[br*OCH + oc] = pb[oc] - a;
    }
}

// ---------------- prim conv GEMM: inline im2col gather + split-bf16 mma ----------------
__device__ __forceinline__ void load_B(uint32_t sb, int buf, int n0, int kc, int K,
                                       size_t wo, int tid)
{
    uint32_t dst0 = sb + buf*STAGEB + 2*TILEB;
#pragma unroll
    for (int i = 0; i < 4; i++) {
        int q = tid + i*256;
        int mat = q >> 9;              // 0:Bh 1:Bl
        int w = q & 511;
        int row = w >> 2, ch = w & 3;
        const __nv_bfloat16* src = (mat ? g_wl : g_wh) + wo + (size_t)(n0+row)*K + kc + ch*8;
        CP_ASYNC16(dst0 + mat*TILEB + row*(TSTRIDE*2) + ch*16, src);
    }
}

__device__ __forceinline__ void gather_A(const float* __restrict__ yb,
                                         const int* rowbase, const int* s_kt,
                                         int kc, int lane, float* f)
{
    int off = s_kt[kc + lane];
#pragma unroll
    for (int j = 0; j < 16; j++) f[j] = yb[rowbase[j] + off];
}
__device__ __forceinline__ void convert_sts_A(char* smem, int buf,
                                              int wid, int lane, const float* f)
{
    char* base = smem + buf*STAGEB + (wid*16)*(TSTRIDE*2) + lane*2;
#pragma unroll
    for (int j = 0; j < 16; j++) {
        float v = f[j];
        __nv_bfloat16 h = __float2bfloat16(v);
        __nv_bfloat16 l = __float2bfloat16(v - __bfloat162float(h));
        char* p = base + j*(TSTRIDE*2);
        *(__nv_bfloat16*)p = h;
        *(__nv_bfloat16*)(p + TILEB) = l;
    }
}

__global__ __launch_bounds__(256) void prim_mma_kernel(int S, int Hp, int H1, int K,
                                                       size_t yo, size_t ko,
                                                       size_t wo, size_t po, int br)
{
    extern __shared__ char smem[];
    int* s_kt = (int*)(smem + GSMEM0);
    uint32_t sb = smem_u32(smem);
    int tid = threadIdx.x, wid = tid >> 5, lane = tid & 31;
    int n0 = (blockIdx.x & 1) << 7;
    int m0 = (int)(blockIdx.x >> 1) << 7;

    for (int k = tid; k < K; k += 256) s_kt[k] = g_ktab[ko + k] & 0xFFFFF;

    // this warp stages rows [wid*16, wid*16+16)
    int rowbase[16];
#pragma unroll
    for (int j = 0; j < 16; j++) {
        int m = m0 + wid*16 + j;
        int b = m / S, s = m - b*S;
        int oy = s / Hp, ox = s - oy*Hp;
        rowbase[j] = b*CC*H1*H1 + (oy*2)*H1 + ox*2;
    }
    __syncthreads();   // s_kt ready

    const float* yb = g_y + yo;

    int wm = (wid & 3) << 5;
    int wn = (wid >> 2) << 6;

    float acc[2][8][4];
#pragma unroll
    for (int mt = 0; mt < 2; mt++)
#pragma unroll
        for (int nb = 0; nb < 8; nb++)
#pragma unroll
            for (int j = 0; j < 4; j++) acc[mt][nb][j] = 0.f;

    int nch = K >> 5;

    // prologue: stage chunk 0
    load_B(sb, 0, n0, 0, K, wo, tid);
    CP_COMMIT();
    {
        float f[16];
        gather_A(yb, rowbase, s_kt, 0, lane, f);
        convert_sts_A(smem, 0, wid, lane, f);
    }
    CP_WAIT0();
    __syncthreads();

    uint32_t aLaneOff = (uint32_t)((lane & 15)*(TSTRIDE*2) + (lane >> 4)*16);
    uint32_t bLaneOff = (uint32_t)((((lane >> 3) & 3)*8 + (lane & 7))*(TSTRIDE*2));

    for (int c = 0; c < nch; c++) {
        int p = c & 1, q = p ^ 1;
        float f[16];
        if (c + 1 < nch) {
            load_B(sb, q, n0, (c + 1) << 5, K, wo, tid);
            CP_COMMIT();
            gather_A(yb, rowbase, s_kt, (c + 1) << 5, lane, f);
        }

        uint32_t st = sb + p*STAGEB;
#pragma unroll
        for (int kk = 0; kk < 2; kk++) {
            uint32_t ah[2][4], al[2][4];
#pragma unroll
            for (int mt = 0; mt < 2; mt++)
                ldmx4(st + (wm + mt*16)*(TSTRIDE*2) + kk*32 + aLaneOff,
                      ah[mt][0], ah[mt][1], ah[mt][2], ah[mt][3]);
            uint32_t bh[8][2], bl[8][2];
#pragma unroll
            for (int g = 0; g < 2; g++)
#pragma unroll
                for (int kh = 0; kh < 2; kh++) {
                    uint32_t r0, r1, r2, r3;
                    ldmx4(st + 2*TILEB + (wn + g*32)*(TSTRIDE*2) + kk*32 + kh*16 + bLaneOff,
                          r0, r1, r2, r3);
                    bh[g*4+0][kh] = r0; bh[g*4+1][kh] = r1;
                    bh[g*4+2][kh] = r2; bh[g*4+3][kh] = r3;
                    ldmx4(st + 3*TILEB + (wn + g*32)*(TSTRIDE*2) + kk*32 + kh*16 + bLaneOff,
                          r0, r1, r2, r3);
                    bl[g*4+0][kh] = r0; bl[g*4+1][kh] = r1;
                    bl[g*4+2][kh] = r2; bl[g*4+3][kh] = r3;
                }
#pragma unroll
            for (int mt = 0; mt < 2; mt++)
#pragma unroll
                for (int nb = 0; nb < 8; nb++)
                    mma16816(acc[mt][nb], ah[mt], bh[nb][0], bh[nb][1]);
#pragma unroll
            for (int mt = 0; mt < 2; mt++)
#pragma unroll
                for (int nb = 0; nb < 8; nb++)
                    mma16816(acc[mt][nb], ah[mt], bl[nb][0], bl[nb][1]);
#pragma unroll
            for (int mt = 0; mt < 2; mt++)
                ldmx4(st + TILEB + (wm + mt*16)*(TSTRIDE*2) + kk*32 + aLaneOff,
                      al[mt][0], al[mt][1], al[mt][2], al[mt][3]);
#pragma unroll
            for (int mt = 0; mt < 2; mt++)
#pragma unroll
                for (int nb = 0; nb < 8; nb++)
                    mma16816(acc[mt][nb], al[mt], bh[nb][0], bh[nb][1]);
        }

        if (c + 1 < nch) {
            convert_sts_A(smem, q, wid, lane, f);
            CP_WAIT0();
        }
        __syncthreads();
    }

    // epilogue: g_p layout [m][oc], bias from BN-folded adjust
    int gr = lane >> 2, tc = lane & 3;
    float* gp = g_p + po;
    const float* badj = g_badj + br*OCH;
#pragma unroll
    for (int mt = 0; mt < 2; mt++) {
        int mA = m0 + wm + mt*16 + gr;
        int mB = mA + 8;
#pragma unroll
        for (int nb = 0; nb < 8; nb++) {
            int oc = n0 + wn + nb*8 + tc*2;
            float bias0 = badj[oc], bias1 = badj[oc+1];
            float2 vA = make_float2(acc[mt][nb][0] + bias0, acc[mt][nb][1] + bias1);
            float2 vB = make_float2(acc[mt][nb][2] + bias0, acc[mt][nb][3] + bias1);
            *reinterpret_cast<float2*>(gp + (size_t)mA*OCH + oc) = vA;
            *reinterpret_cast<float2*>(gp + (size_t)mB*OCH + oc) = vB;
        }
    }
}

// ---------------- squash primary capsules ----------------
__global__ void squash_u_kernel(int S, int R, size_t po, size_t uo) {
    int idx = blockIdx.x*blockDim.x + threadIdx.x;
    if (idx >= BATCH*R) return;
    int r = idx % R, b = idx / R;
    int c32 = r / S, s = r - c32*S;
    const float* pp = g_p + po + (size_t)(b*S + s)*OCH + c32;
    float t[8]; float sn = 0.f;
#pragma unroll
    for (int i = 0; i < 8; i++) {
        t[i] = pp[i*32];
        sn += t[i]*t[i];
    }
    float scale = sn/(1.f + sn) * rsqrtf(sn + 1e-12f);
    float* up = g_u + uo + (size_t)idx*8;
#pragma unroll
    for (int i = 0; i < 8; i++)
        up[i] = t[i]*scale;
}

// ---------------- fused priors + dynamic routing ----------------
__global__ void routing_fused_kernel(const float* __restrict__ dw, int R, int br, size_t uo) {
    int b = blockIdx.x, n = blockIdx.y;
    extern __shared__ float sm[];
    float* P    = sm;
    float* blog = P + R*16;
    float* wred = blog + R;
    float* vv   = wred + 128;
    float* sred = vv + 16;
    float* scal = sred + 8;

    int tid = threadIdx.x;
    // build priors tile in smem: P[r][o] = sum_i u[b][r][i] * dw[n][r][i][o]
    for (int idx = tid; idx < R*16; idx += 256) {
        int r = idx >> 4, o = idx & 15;
        const float* wr = dw + (((size_t)n*R + r) << 7) + o;
        const float* ur = g_u + uo + ((size_t)b*R + r)*8;
        float s = 0.f;
#pragma unroll
        for (int i = 0; i < 8; i++) s += ur[i]*wr[i*16];
        P[idx] = s;
    }
    for (int r = tid; r < R; r += 256) blog[r] = 0.f;
    __syncthreads();

    for (int it = 0; it < 3; it++) {
        float mx = -1e30f;
        for (int r = tid; r < R; r += 256) mx = fmaxf(mx, blog[r]);
#pragma unroll
        for (int off = 16; off; off >>= 1)
            mx = fmaxf(mx, __shfl_xor_sync(0xffffffffu, mx, off));
        if ((tid & 31) == 0) sred[tid >> 5] = mx;
        __syncthreads();
        if (tid == 0) {
            float m = sred[0];
            for (int w2 = 1; w2 < 8; w2++) m = fmaxf(m, sred[w2]);
            scal[0] = m;
        }
        __syncthreads();
        float gmax = scal[0];
        float se = 0.f;
        for (int r = tid; r < R; r += 256) se += expf(blog[r] - gmax);
#pragma unroll
        for (int off = 16; off; off >>= 1)
            se += __shfl_xor_sync(0xffffffffu, se, off);
        if ((tid & 31) == 0) sred[tid >> 5] = se;
        __syncthreads();
        if (tid == 0) {
            float s = 0.f;
            for (int w2 = 0; w2 < 8; w2++) s += sred[w2];
            scal[1] = 1.f/s;
        }
        __syncthreads();
        float isum = scal[1];
        float acc[16];
#pragma unroll
        for (int o = 0; o < 16; o++) acc[o] = 0.f;
        for (int r = tid; r < R; r += 256) {
            float c = expf(blog[r] - gmax)*isum;
            const float* pr = P + r*16;
#pragma unroll
            for (int o = 0; o < 16; o++) acc[o] += c*pr[o];
        }
#pragma unroll
        for (int o = 0; o < 16; o++) {
            float v = acc[o];
#pragma unroll
            for (int off = 16; off; off >>= 1)
                v += __shfl_xor_sync(0xffffffffu, v, off);
            acc[o] = v;
        }
        if ((tid & 31) == 0)
#pragma unroll
            for (int o = 0; o < 16; o++) wred[(tid >> 5)*16 + o] = acc[o];
        __syncthreads();
        if (tid == 0) {
            float s16[16]; float sn = 0.f;
#pragma unroll
            for (int o = 0; o < 16; o++) {
                float s = 0.f;
                for (int w2 = 0; w2 < 8; w2++) s += wred[w2*16 + o];
                s16[o] = s; sn += s*s;
            }
            float sc = sn/(1.f + sn) * rsqrtf(sn + 1e-12f);
#pragma unroll
            for (int o = 0; o < 16; o++) vv[o] = s16[o]*sc;
        }
        __syncthreads();
        if (it < 2) {
            for (int r = tid; r < R; r += 256) {
                const float* pr = P + r*16;
                float d = 0.f;
#pragma unroll
                for (int o = 0; o < 16; o++) d += pr[o]*vv[o];
                blog[r] += d;
            }
            __syncthreads();
        }
    }
    if (tid == 0) {
        float s = 0.f;
#pragma unroll
        for (int o = 0; o < 16; o++) s += vv[o]*vv[o];
        g_len[br*BATCH*NCLS + b*NCLS + n] = sqrtf(s + 1e-12f);
    }
}

// ---------------- final ----------------
__global__ void final_kernel(float* __restrict__ out) {
    int b = blockIdx.x*blockDim.x + threadIdx.x;
    if (b >= BATCH) return;
    float l[NCLS]; float mx = -1e30f;
#pragma unroll
    for (int n = 0; n < NCLS; n++) {
        l[n] = g_len[0*BATCH*NCLS + b*NCLS + n]
             + g_len[1*BATCH*NCLS + b*NCLS + n]
             + g_len[2*BATCH*NCLS + b*NCLS + n];
        mx = fmaxf(mx, l[n]);
    }
    float s = 0.f;
#pragma unroll
    for (int n = 0; n < NCLS; n++) { l[n] = expf(l[n] - mx); s += l[n]; }
    float inv = 1.f/s;
#pragma unroll
    for (int n = 0; n < NCLS; n++) out[b*NCLS + n] = l[n]*inv;
}

// ---------------- host driver ----------------
struct BranchCfg {
    int src;
    int H, k1, H1, kp, Hp, S, R, K;
    int iw, br;
    size_t yo, ko, wo, po, uo;
};

static void run_branch(const BranchCfg& c, void* const* d_in, const float* x,
                       cudaStream_t st)
{
    const float* cw = (const float*)d_in[c.iw + 0];
    const float* cb = (const float*)d_in[c.iw + 1];
    const float* pw = (const float*)d_in[c.iw + 2];
    const float* pb = (const float*)d_in[c.iw + 3];
    const float* dw = (const float*)d_in[c.iw + 4];

    int HW = c.H1*c.H1;
    prep_ktab_kernel<<<(c.K + 255)/256, 256, 0, st>>>(c.K, c.kp, c.H1, c.ko);
    if (c.k1 == 3)      convA_smem<3, 7, 5  ><<<BATCH, 256, 0, st>>>(x, c.src, cw, cb, c.yo);
    else if (c.k1 == 5) convA_smem<5, 14, 10><<<BATCH, 256, 0, st>>>(x, c.src, cw, cb, c.yo);
    else                convA_smem<9, 28, 20><<<BATCH, 256, 0, st>>>(x, c.src, cw, cb, c.yo);
    bn_partial_kernel<<<dim3(CC, 8), 256, 0, st>>>(HW, c.yo, c.br);
    bn_final_kernel<<<1, CC, 0, st>>>(HW, c.br);

    prep_w_kernel<<<(OCH*c.K + 255)/256, 256, 0, st>>>(pw, c.K, c.wo, c.ko, c.br);
    prep_badj_kernel<<<OCH, 256, 0, st>>>(pw, pb, c.K, c.ko, c.br);

    int M = BATCH*c.S;
    int gsmem = GSMEM0 + c.K*4;
    prim_mma_kernel<<<2*(M/128), 256, gsmem, st>>>(c.S, c.Hp, c.H1, c.K,
                                                   c.yo, c.ko, c.wo, c.po, c.br);

    squash_u_kernel<<<(BATCH*c.R + 255)/256, 256, 0, st>>>(c.S, c.R, c.po, c.uo);

    int smemR = (c.R*17 + 128 + 16 + 8 + 2)*(int)sizeof(float);
    dim3 rgrid(BATCH, NCLS);
    routing_fused_kernel<<<rgrid, 256, smemR, st>>>(dw, c.R, c.br, c.uo);
}

extern "C" void kernel_launch(void* const* d_in, const int* in_sizes, int n_in,
                              void* d_out, int out_size)
{
    (void)in_sizes; (void)n_in; (void)out_size;
    const float* x = (const float*)d_in[0];
    float* out = (float*)d_out;

    static cudaStream_t st[3] = {0, 0, 0};
    static cudaEvent_t evRoot = 0, evPool = 0, evDone[3] = {0, 0, 0};
    if (!st[0]) {
        for (int i = 0; i < 3; i++)
            cudaStreamCreateWithFlags(&st[i], cudaStreamNonBlocking);
        cudaEventCreateWithFlags(&evRoot, cudaEventDisableTiming);
        cudaEventCreateWithFlags(&evPool, cudaEventDisableTiming);
        for (int i = 0; i < 3; i++)
            cudaEventCreateWithFlags(&evDone[i], cudaEventDisableTiming);
    }

    cudaFuncSetAttribute(routing_fused_kernel, cudaFuncAttributeMaxDynamicSharedMemorySize, 96*1024);
    cudaFuncSetAttribute(prim_mma_kernel, cudaFuncAttributeMaxDynamicSharedMemorySize,
                         GSMEM0 + 10368*4);

    //                src  H  k1 H1  kp Hp  S    R      K   iw br   yo       ko    wo       po      uo
    BranchCfg b1 = {   2,  7, 3,  5,  3, 2,  4,  128,  1152,  1, 0, 0,       0,    0,       0,      0      };
    BranchCfg b2 = {   1, 14, 5, 10,  5, 3,  9,  288,  3200,  6, 1, 819200,  1152, 294912,  262144, 262144 };
    BranchCfg b3 = {   0, 28, 9, 20,  9, 6, 36, 1152, 10368, 11, 2, 4096000, 4352, 1114112, 851968, 851968 };

    cudaEventRecord(evRoot, 0);
    for (int i = 0; i < 3; i++) cudaStreamWaitEvent(st[i], evRoot, 0);

    pool2_kernel<<<(BATCH*14*14 + 255)/256, 256, 0, st[1]>>>(x);
    cudaEventRecord(evPool, st[1]);
    cudaStreamWaitEvent(st[0], evPool, 0);
    pool1_kernel<<<(BATCH*7*7 + 255)/256, 256, 0, st[0]>>>();

    run_branch(b3, d_in, x, st[2]);
    run_branch(b2, d_in, x, st[1]);
    run_branch(b1, d_in, x, st[0]);

    for (int i = 0; i < 3; i++) {
        cudaEventRecord(evDone[i], st[i]);
        cudaStreamWaitEvent(0, evDone[i], 0);
    }
    final_kernel<<<1, 256>>>(out);
}